// round 1
// baseline (speedup 1.0000x reference)
#include <cuda_runtime.h>
#include <math.h>

#define T_ 128
#define N_ 256
#define L_ 256
#define H_ 256
#define COND_ 64
#define ROWS_ (T_ * N_)   // 32768
#define OUTW_ 770         // 1 + 1 + H + L + L

// ---------------- scratch (single __device__ symbol, no allocations) -------
// XIN: ROWS*320 | XA: ROWS*256 | XB: ROWS*256 | GI: ROWS*768 | KB: ROWS*256 |
// WB: N*T*L = ROWS*256 | CC: ROWS | HB: 2*N*H
#define XIN_OFF 0L
#define XA_OFF  (XIN_OFF + (long)ROWS_ * 320)
#define XB_OFF  (XA_OFF  + (long)ROWS_ * 256)
#define GI_OFF  (XB_OFF  + (long)ROWS_ * 256)
#define KB_OFF  (GI_OFF  + (long)ROWS_ * 768)
#define WB_OFF  (KB_OFF  + (long)ROWS_ * 256)
#define CC_OFF  (WB_OFF  + (long)ROWS_ * 256)
#define HB_OFF  (CC_OFF  + (long)ROWS_)
#define SCRATCH_FLOATS (HB_OFF + 2L * N_ * H_)

__device__ float g_scratch[SCRATCH_FLOATS];

// ---------------------------------------------------------------------------
// t=0: generic p_init handling (new-episode rows get e_0), r0 = p_init @ M[n],
// cc0 = p_init . C[n]
__global__ __launch_bounds__(256) void t0_kernel(
    const float* __restrict__ p0, const float* __restrict__ M,
    const float* __restrict__ C, float* __restrict__ XIN, float* __restrict__ CC)
{
    int n = blockIdx.x;
    int tid = threadIdx.x;
    __shared__ float red[256];
    __shared__ float ps[256];

    float v = p0[(long)n * L_ + tid];
    red[tid] = (v != 0.f) ? 1.f : 0.f;
    __syncthreads();
    for (int s = 128; s > 0; s >>= 1) {
        if (tid < s) red[tid] += red[tid + s];
        __syncthreads();
    }
    bool any = red[0] > 0.f;
    float pl = v;
    if (tid == 0 && !any) pl = 1.f;
    ps[tid] = pl;
    __syncthreads();

    // r0[h] = sum_l ps[l] * M[n, l, h]   (h = tid)
    float acc = 0.f;
    const float* Mn = M + (long)n * L_ * H_;
    for (int l = 0; l < L_; l++)
        acc = fmaf(ps[l], Mn[(long)l * H_ + tid], acc);
    XIN[(long)n * 320 + 64 + tid] = acc;

    red[tid] = ps[tid] * C[(long)n * L_ + tid];
    __syncthreads();
    for (int s = 128; s > 0; s >>= 1) {
        if (tid < s) red[tid] += red[tid + s];
        __syncthreads();
    }
    if (tid == 0) CC[n] = red[0];
}

// ---------------------------------------------------------------------------
// builds XIN rows: [cond(64) | r(256)], and CC for t>=1 (one-hot gather)
__global__ __launch_bounds__(256) void gather_kernel(
    const float* __restrict__ cond, const float* __restrict__ M,
    const float* __restrict__ C, const int* __restrict__ actions,
    float* __restrict__ XIN, float* __restrict__ CC)
{
    long idx = blockIdx.x;          // t*N + n
    int t = (int)(idx / N_), n = (int)(idx % N_);
    int tid = threadIdx.x;
    float* xrow = XIN + idx * 320;
    if (tid < 64) xrow[tid] = cond[idx * COND_ + tid];
    if (t > 0) {
        int a = actions[idx - N_];  // actions[t-1, n]
        xrow[64 + tid] = M[((long)n * L_ + a) * H_ + tid];
        if (tid == 0) CC[idx] = C[(long)n * L_ + a];
    }
}

// ---------------------------------------------------------------------------
// generic fp32 tiled GEMM: C = act(A @ B (+bias)), optional B^T, batched via z
template <bool TRANSB, bool RELU>
__global__ __launch_bounds__(256) void gemm_kernel(
    const float* __restrict__ A, const float* __restrict__ B,
    const float* __restrict__ bias, float* __restrict__ C,
    int M, int N, int K, int lda, int ldb, int ldc,
    long batchA, long batchB, long batchC)
{
    constexpr int BM = 64, BN = 64, BK = 16;
    __shared__ float As[BK][BM + 4];
    __shared__ float Bs[BK][BN + 4];

    long bz = blockIdx.z;
    A += bz * batchA; B += bz * batchB; C += bz * batchC;
    int m0 = blockIdx.x * BM, n0 = blockIdx.y * BN;
    int tid = threadIdx.x;
    int tx = tid & 15, ty = tid >> 4;

    float acc[4][4];
#pragma unroll
    for (int i = 0; i < 4; i++)
#pragma unroll
        for (int j = 0; j < 4; j++) acc[i][j] = 0.f;

    for (int k0 = 0; k0 < K; k0 += BK) {
        {
            int kk = tid & 15;
            int mb = tid >> 4;
#pragma unroll
            for (int i = 0; i < 4; i++) {
                int mm = mb + i * 16;
                As[kk][mm] = A[(long)(m0 + mm) * lda + (k0 + kk)];
            }
        }
        if (!TRANSB) {
            int nn = tid & 63;
            int kb = tid >> 6;
#pragma unroll
            for (int i = 0; i < 4; i++) {
                int kk = kb + i * 4;
                Bs[kk][nn] = B[(long)(k0 + kk) * ldb + (n0 + nn)];
            }
        } else {
            int kk = tid & 15;
            int nb = tid >> 4;
#pragma unroll
            for (int i = 0; i < 4; i++) {
                int nn = nb + i * 16;
                Bs[kk][nn] = B[(long)(n0 + nn) * ldb + (k0 + kk)];
            }
        }
        __syncthreads();
#pragma unroll
        for (int k = 0; k < BK; k++) {
            float a[4], b[4];
#pragma unroll
            for (int i = 0; i < 4; i++) a[i] = As[k][ty * 4 + i];
#pragma unroll
            for (int j = 0; j < 4; j++) b[j] = Bs[k][tx * 4 + j];
#pragma unroll
            for (int i = 0; i < 4; i++)
#pragma unroll
                for (int j = 0; j < 4; j++) acc[i][j] = fmaf(a[i], b[j], acc[i][j]);
        }
        __syncthreads();
    }

#pragma unroll
    for (int i = 0; i < 4; i++) {
        int m = m0 + ty * 4 + i;
#pragma unroll
        for (int j = 0; j < 4; j++) {
            int n = n0 + tx * 4 + j;
            float v = acc[i][j];
            if (bias) v += bias[n];
            if (RELU) v = fmaxf(v, 0.f);
            C[(long)m * ldc + n] = v;
        }
    }
}

// ---------------------------------------------------------------------------
// one GRU step: gh = h @ W_hh^T, combine with precomputed gi -> h_new
// grid (16 j-tiles, 16 n-tiles), 256 threads; tile = 16n x 16j x (3 gates)
__global__ __launch_bounds__(256) void gru_step_kernel(
    const float* __restrict__ GI, float* __restrict__ HB,
    const float* __restrict__ h0, const float* __restrict__ W_hh,
    const float* __restrict__ b_hh, float* __restrict__ out, int t)
{
    const int j0 = blockIdx.x * 16;
    const int n0 = blockIdx.y * 16;
    const float* hin = (t == 0) ? h0 : (HB + (((t & 1) ^ 1)) * (N_ * H_));
    float* hout = HB + (t & 1) * (N_ * H_);

    __shared__ float hs[16][64];
    __shared__ float ws[48][68];

    int tid = threadIdx.x;
    int jj = tid & 15, nn = tid >> 4;
    float acc0 = 0.f, acc1 = 0.f, acc2 = 0.f;

    for (int k0 = 0; k0 < H_; k0 += 64) {
        {
            int n = tid >> 4;
            int k = (tid & 15) * 4;
            *(float4*)&hs[n][k] =
                *(const float4*)&hin[(long)(n0 + n) * H_ + k0 + k];
        }
#pragma unroll
        for (int i = 0; i < 3; i++) {
            int e = tid + i * 256;       // float4 index 0..767
            int r = e >> 4;              // row 0..47
            int k = (e & 15) * 4;
            int gate = r >> 4, jr = r & 15;
            int g = gate * 256 + j0 + jr;
            *(float4*)&ws[r][k] = *(const float4*)&W_hh[(long)g * H_ + k0 + k];
        }
        __syncthreads();
#pragma unroll
        for (int k = 0; k < 64; k += 4) {
            float4 hv = *(float4*)&hs[nn][k];
            float4 w0 = *(float4*)&ws[jj][k];
            float4 w1 = *(float4*)&ws[16 + jj][k];
            float4 w2 = *(float4*)&ws[32 + jj][k];
            acc0 = fmaf(hv.x, w0.x, fmaf(hv.y, w0.y, fmaf(hv.z, w0.z, fmaf(hv.w, w0.w, acc0))));
            acc1 = fmaf(hv.x, w1.x, fmaf(hv.y, w1.y, fmaf(hv.z, w1.z, fmaf(hv.w, w1.w, acc1))));
            acc2 = fmaf(hv.x, w2.x, fmaf(hv.y, w2.y, fmaf(hv.z, w2.z, fmaf(hv.w, w2.w, acc2))));
        }
        __syncthreads();
    }

    int n = n0 + nn, j = j0 + jj;
    const float* gi = GI + ((long)t * N_ + n) * 768;
    float ghr = acc0 + b_hh[j];
    float ghz = acc1 + b_hh[256 + j];
    float ghn = acc2 + b_hh[512 + j];
    float rg = 1.f / (1.f + expf(-(gi[j] + ghr)));
    float z  = 1.f / (1.f + expf(-(gi[256 + j] + ghz)));
    float nv = tanhf(gi[512 + j] + rg * ghn);
    float hprev = hin[(long)n * H_ + j];
    float hnew = (1.f - z) * nv + z * hprev;
    hout[(long)n * H_ + j] = hnew;
    out[((long)t * N_ + n) * OUTW_ + 2 + j] = hnew;
}

// ---------------------------------------------------------------------------
// per (t,n): softmax(w*cc), one-hot p, action, value v = h.Wc + bc
__global__ __launch_bounds__(256) void epilogue_kernel(
    const float* __restrict__ WB, const float* __restrict__ CC,
    const int* __restrict__ actions, const float* __restrict__ Wc,
    const float* __restrict__ bc, float* __restrict__ out)
{
    long idx = blockIdx.x;          // t*N + n
    int t = (int)(idx / N_), n = (int)(idx % N_);
    int l = threadIdx.x;
    __shared__ float red[256];

    float w = WB[((long)n * T_ + t) * L_ + l] * CC[idx];
    red[l] = w;
    __syncthreads();
    for (int s = 128; s > 0; s >>= 1) {
        if (l < s) red[l] = fmaxf(red[l], red[l + s]);
        __syncthreads();
    }
    float mx = red[0];
    __syncthreads();
    float e = expf(w - mx);
    red[l] = e;
    __syncthreads();
    for (int s = 128; s > 0; s >>= 1) {
        if (l < s) red[l] += red[l + s];
        __syncthreads();
    }
    float sum = red[0];
    __syncthreads();

    long base = idx * OUTW_;
    out[base + 2 + 256 + l] = e / sum;
    int a = actions[idx];
    out[base + 2 + 512 + l] = (l == a) ? 1.f : 0.f;

    red[l] = out[base + 2 + l] * Wc[l];
    __syncthreads();
    for (int s = 128; s > 0; s >>= 1) {
        if (l < s) red[l] += red[l + s];
        __syncthreads();
    }
    if (l == 0) {
        out[base + 1] = red[0] + bc[0];
        out[base + 0] = (float)a;
    }
}

// ---------------------------------------------------------------------------
extern "C" void kernel_launch(void* const* d_in, const int* in_sizes, int n_in,
                              void* d_out, int out_size)
{
    const float* cond = (const float*)d_in[0];
    const float* M    = (const float*)d_in[1];
    const float* Km   = (const float*)d_in[2];
    const float* Cm   = (const float*)d_in[3];
    const float* h0   = (const float*)d_in[4];
    const float* p0   = (const float*)d_in[5];
    const float* W0   = (const float*)d_in[6];
    const float* b0   = (const float*)d_in[7];
    const float* W1   = (const float*)d_in[8];
    const float* b1   = (const float*)d_in[9];
    const float* W2   = (const float*)d_in[10];
    const float* b2   = (const float*)d_in[11];
    const float* W_ih = (const float*)d_in[12];
    const float* W_hh = (const float*)d_in[13];
    const float* b_ih = (const float*)d_in[14];
    const float* b_hh = (const float*)d_in[15];
    const float* Wa   = (const float*)d_in[16];
    const float* ba   = (const float*)d_in[17];
    const float* Wc   = (const float*)d_in[18];
    const float* bc   = (const float*)d_in[19];
    const int* actions = (const int*)d_in[20];
    float* out = (float*)d_out;

    float* base = nullptr;
    cudaGetSymbolAddress((void**)&base, g_scratch);
    float* XIN = base + XIN_OFF;
    float* XA  = base + XA_OFF;
    float* XB  = base + XB_OFF;
    float* GI  = base + GI_OFF;
    float* KB  = base + KB_OFF;
    float* WB  = base + WB_OFF;
    float* CC  = base + CC_OFF;
    float* HB  = base + HB_OFF;

    // phase A: inputs -> gi (fully parallel over T*N)
    t0_kernel<<<N_, 256>>>(p0, M, Cm, XIN, CC);
    gather_kernel<<<ROWS_, 256>>>(cond, M, Cm, actions, XIN, CC);
    gemm_kernel<false, true><<<dim3(ROWS_ / 64, 4, 1), 256>>>(
        XIN, W0, b0, XA, ROWS_, 256, 320, 320, 256, 256, 0, 0, 0);
    gemm_kernel<false, true><<<dim3(ROWS_ / 64, 4, 1), 256>>>(
        XA, W1, b1, XB, ROWS_, 256, 256, 256, 256, 256, 0, 0, 0);
    gemm_kernel<false, true><<<dim3(ROWS_ / 64, 4, 1), 256>>>(
        XB, W2, b2, XA, ROWS_, 256, 256, 256, 256, 256, 0, 0, 0);
    gemm_kernel<true, false><<<dim3(ROWS_ / 64, 12, 1), 256>>>(
        XA, W_ih, b_ih, GI, ROWS_, 768, 256, 256, 256, 768, 0, 0, 0);

    // phase B: sequential GRU (128 dependent steps, stream-ordered)
    for (int t = 0; t < T_; t++)
        gru_step_kernel<<<dim3(16, 16), 256>>>(GI, HB, h0, W_hh, b_hh, out, t);

    // phase C: actor head (parallel again)
    gemm_kernel<false, false><<<dim3(ROWS_ / 64, 4, 1), 256>>>(
        out + 2, Wa, ba, KB, ROWS_, 256, 256, OUTW_, 256, 256, 0, 0, 0);
    gemm_kernel<true, false><<<dim3(2, 4, N_), 256>>>(
        KB, Km, nullptr, WB, T_, 256, 256, N_ * 256, 256, 256,
        256L, (long)L_ * H_, (long)T_ * L_);
    epilogue_kernel<<<ROWS_, 256>>>(WB, CC, actions, Wc, bc, out);
}

// round 2
// speedup vs baseline: 1.1607x; 1.1607x over previous
#include <cuda_runtime.h>
#include <math.h>

#define T_ 128
#define N_ 256
#define L_ 256
#define H_ 256
#define COND_ 64
#define ROWS_ (T_ * N_)   // 32768
#define OUTW_ 770         // 1 + 1 + H + L + L

// ---------------- scratch (single __device__ symbol, no allocations) -------
#define XIN_OFF 0L
#define XA_OFF  (XIN_OFF + (long)ROWS_ * 320)
#define XB_OFF  (XA_OFF  + (long)ROWS_ * 256)
#define GI_OFF  (XB_OFF  + (long)ROWS_ * 256)
#define KB_OFF  (GI_OFF  + (long)ROWS_ * 768)
#define WB_OFF  (KB_OFF  + (long)ROWS_ * 256)
#define CC_OFF  (WB_OFF  + (long)ROWS_ * 256)
#define HB_OFF  (CC_OFF  + (long)ROWS_)
#define SCRATCH_FLOATS (HB_OFF + 2L * N_ * H_)

__device__ float g_scratch[SCRATCH_FLOATS];
__device__ unsigned g_bar[2];   // [0]=arrive counter, [1]=epoch

// ---------------- packed fp32x2 helpers (sm_103a) ---------------------------
#define FMA2(d, a, b) \
    asm("fma.rn.f32x2 %0, %1, %2, %0;" : "+l"(d) : "l"(a), "l"(b))
#define DUP2(d, x) \
    asm("mov.b64 %0, {%1, %1};" : "=l"(d) : "f"(x))
#define UNPACK2(lo, hi, v) \
    asm("mov.b64 {%0, %1}, %2;" : "=f"(lo), "=f"(hi) : "l"(v))

// ---------------------------------------------------------------------------
// t=0: generic p_init handling (new-episode rows get e_0)
__global__ __launch_bounds__(256) void t0_kernel(
    const float* __restrict__ p0, const float* __restrict__ M,
    const float* __restrict__ C, float* __restrict__ XIN, float* __restrict__ CC)
{
    int n = blockIdx.x;
    int tid = threadIdx.x;
    __shared__ float red[256];
    __shared__ float ps[256];

    float v = p0[(long)n * L_ + tid];
    red[tid] = (v != 0.f) ? 1.f : 0.f;
    __syncthreads();
    for (int s = 128; s > 0; s >>= 1) {
        if (tid < s) red[tid] += red[tid + s];
        __syncthreads();
    }
    bool any = red[0] > 0.f;
    float pl = v;
    if (tid == 0 && !any) pl = 1.f;
    ps[tid] = pl;
    __syncthreads();

    float acc = 0.f;
    const float* Mn = M + (long)n * L_ * H_;
    for (int l = 0; l < L_; l++)
        acc = fmaf(ps[l], Mn[(long)l * H_ + tid], acc);
    XIN[(long)n * 320 + 64 + tid] = acc;

    red[tid] = ps[tid] * C[(long)n * L_ + tid];
    __syncthreads();
    for (int s = 128; s > 0; s >>= 1) {
        if (tid < s) red[tid] += red[tid + s];
        __syncthreads();
    }
    if (tid == 0) CC[n] = red[0];
}

// ---------------------------------------------------------------------------
__global__ __launch_bounds__(256) void gather_kernel(
    const float* __restrict__ cond, const float* __restrict__ M,
    const float* __restrict__ C, const int* __restrict__ actions,
    float* __restrict__ XIN, float* __restrict__ CC)
{
    long idx = blockIdx.x;          // t*N + n
    int t = (int)(idx / N_), n = (int)(idx % N_);
    int tid = threadIdx.x;
    float* xrow = XIN + idx * 320;
    if (tid < 64) xrow[tid] = cond[idx * COND_ + tid];
    if (t > 0) {
        int a = actions[idx - N_];  // actions[t-1, n]
        xrow[64 + tid] = M[((long)n * L_ + a) * H_ + tid];
        if (tid == 0) CC[idx] = C[(long)n * L_ + a];
    }
}

// ---------------------------------------------------------------------------
// generic fp32 tiled GEMM with packed f32x2 FMAs
template <bool TRANSB, bool RELU>
__global__ __launch_bounds__(256) void gemm_kernel(
    const float* __restrict__ A, const float* __restrict__ B,
    const float* __restrict__ bias, float* __restrict__ C,
    int M, int N, int K, int lda, int ldb, int ldc,
    long batchA, long batchB, long batchC)
{
    constexpr int BM = 64, BN = 64, BK = 16;
    __shared__ float As[BK][BM + 4];
    __shared__ float Bs[BK][BN + 4];

    long bz = blockIdx.z;
    A += bz * batchA; B += bz * batchB; C += bz * batchC;
    int m0 = blockIdx.x * BM, n0 = blockIdx.y * BN;
    int tid = threadIdx.x;
    int tx = tid & 15, ty = tid >> 4;

    unsigned long long accp[4][2];
#pragma unroll
    for (int i = 0; i < 4; i++) { accp[i][0] = 0ull; accp[i][1] = 0ull; }

    for (int k0 = 0; k0 < K; k0 += BK) {
        {
            int kk = tid & 15;
            int mb = tid >> 4;
#pragma unroll
            for (int i = 0; i < 4; i++) {
                int mm = mb + i * 16;
                As[kk][mm] = A[(long)(m0 + mm) * lda + (k0 + kk)];
            }
        }
        if (!TRANSB) {
            int nn = tid & 63;
            int kb = tid >> 6;
#pragma unroll
            for (int i = 0; i < 4; i++) {
                int kk = kb + i * 4;
                Bs[kk][nn] = B[(long)(k0 + kk) * ldb + (n0 + nn)];
            }
        } else {
            int kk = tid & 15;
            int nb = tid >> 4;
#pragma unroll
            for (int i = 0; i < 4; i++) {
                int nn = nb + i * 16;
                Bs[kk][nn] = B[(long)(n0 + nn) * ldb + (k0 + kk)];
            }
        }
        __syncthreads();
#pragma unroll
        for (int k = 0; k < BK; k++) {
            float4 av = *(float4*)&As[k][ty * 4];
            unsigned long long bp0 = *(unsigned long long*)&Bs[k][tx * 4];
            unsigned long long bp1 = *(unsigned long long*)&Bs[k][tx * 4 + 2];
            unsigned long long ad;
            DUP2(ad, av.x); FMA2(accp[0][0], ad, bp0); FMA2(accp[0][1], ad, bp1);
            DUP2(ad, av.y); FMA2(accp[1][0], ad, bp0); FMA2(accp[1][1], ad, bp1);
            DUP2(ad, av.z); FMA2(accp[2][0], ad, bp0); FMA2(accp[2][1], ad, bp1);
            DUP2(ad, av.w); FMA2(accp[3][0], ad, bp0); FMA2(accp[3][1], ad, bp1);
        }
        __syncthreads();
    }

#pragma unroll
    for (int i = 0; i < 4; i++) {
        int m = m0 + ty * 4 + i;
        float c0, c1, c2, c3;
        UNPACK2(c0, c1, accp[i][0]);
        UNPACK2(c2, c3, accp[i][1]);
        float vals[4] = {c0, c1, c2, c3};
#pragma unroll
        for (int j = 0; j < 4; j++) {
            int n = n0 + tx * 4 + j;
            float v = vals[j];
            if (bias) v += bias[n];
            if (RELU) v = fmaxf(v, 0.f);
            C[(long)m * ldc + n] = v;
        }
    }
}

// ---------------------------------------------------------------------------
// persistent GRU: 128 blocks (16 j-tiles x 8 n-tiles), W_hh slice cached in
// smem once (k-transposed, f32x2-packed), 128 timesteps with grid barrier.
#define GRU_BLOCKS 128
#define HS_STRIDE 260

__device__ __forceinline__ float sigmf(float x) { return 1.f / (1.f + expf(-x)); }

__global__ __launch_bounds__(256) void gru_persistent(
    const float* __restrict__ GI, float* __restrict__ HB,
    const float* __restrict__ h0, const float* __restrict__ W_hh,
    const float* __restrict__ b_hh, float* __restrict__ out)
{
    extern __shared__ float smem[];
    float2* wp = (float2*)smem;                 // [128 kpairs][48 rows]
    float* hs = smem + 2 * 128 * 48;            // [32][HS_STRIDE]

    int tid = threadIdx.x;
    int jt = blockIdx.x & 15, nt = blockIdx.x >> 4;
    int j0 = jt * 16, n0 = nt * 32;
    int jj = tid & 15, nn = tid >> 4;
    int j = j0 + jj;
    int na = n0 + nn, nb = n0 + nn + 16;

    // load W slice once: wp[kp][g*16+jr] = (W_hh[g*256+j0+jr][2kp], [2kp+1])
    for (int e = tid; e < 48 * 64; e += 256) {
        int r = e >> 6;          // 0..47
        int c = e & 63;          // float4 chunk over k
        int g = r >> 4, jr = r & 15;
        float4 v = *(const float4*)&W_hh[(long)(g * 256 + j0 + jr) * 256 + c * 4];
        wp[(2 * c + 0) * 48 + r] = make_float2(v.x, v.y);
        wp[(2 * c + 1) * 48 + r] = make_float2(v.z, v.w);
    }
    float bhr = b_hh[j], bhz = b_hh[256 + j], bhn = b_hh[512 + j];

    for (int t = 0; t < T_; t++) {
        const float* hin = (t == 0) ? h0 : (HB + ((t & 1) ^ 1) * (N_ * H_));
        float* hout = HB + (t & 1) * (N_ * H_);

        // load h tile [n0..n0+32) x 256 into smem (coalesced float4)
        {
            int n = tid >> 3, f = tid & 7;
            const float* src = hin + (long)(n0 + n) * H_;
            float* dst = hs + n * HS_STRIDE;
#pragma unroll
            for (int i = 0; i < 8; i++) {
                int c = (f + i * 8) * 4;
                *(float4*)&dst[c] = *(const float4*)&src[c];
            }
        }
        // prefetch gi for this (t, n, j)
        const float* gia = GI + ((long)t * N_ + na) * 768;
        const float* gib = GI + ((long)t * N_ + nb) * 768;
        float gra = gia[j], gza = gia[256 + j], gna = gia[512 + j];
        float grb = gib[j], gzb = gib[256 + j], gnb = gib[512 + j];
        __syncthreads();

        unsigned long long a0 = 0, a1 = 0, a2 = 0, b0 = 0, b1 = 0, b2 = 0;
        const unsigned long long* ha =
            (const unsigned long long*)(hs + nn * HS_STRIDE);
        const unsigned long long* hbp =
            (const unsigned long long*)(hs + (nn + 16) * HS_STRIDE);
#pragma unroll 4
        for (int kp = 0; kp < 128; kp++) {
            unsigned long long hva = ha[kp];
            unsigned long long hvb = hbp[kp];
            const unsigned long long* w =
                (const unsigned long long*)(wp + kp * 48);
            unsigned long long w0 = w[jj], w1 = w[16 + jj], w2 = w[32 + jj];
            FMA2(a0, hva, w0); FMA2(a1, hva, w1); FMA2(a2, hva, w2);
            FMA2(b0, hvb, w0); FMA2(b1, hvb, w1); FMA2(b2, hvb, w2);
        }
        float lo, hi;
        UNPACK2(lo, hi, a0); float ghra = lo + hi + bhr;
        UNPACK2(lo, hi, a1); float ghza = lo + hi + bhz;
        UNPACK2(lo, hi, a2); float ghna = lo + hi + bhn;
        UNPACK2(lo, hi, b0); float ghrb = lo + hi + bhr;
        UNPACK2(lo, hi, b1); float ghzb = lo + hi + bhz;
        UNPACK2(lo, hi, b2); float ghnb = lo + hi + bhn;

        {
            float rg = sigmf(gra + ghra);
            float z  = sigmf(gza + ghza);
            float nv = tanhf(gna + rg * ghna);
            float hp = hs[nn * HS_STRIDE + j];
            float hn = (1.f - z) * nv + z * hp;
            hout[(long)na * H_ + j] = hn;
            out[((long)t * N_ + na) * OUTW_ + 2 + j] = hn;
        }
        {
            float rg = sigmf(grb + ghrb);
            float z  = sigmf(gzb + ghzb);
            float nv = tanhf(gnb + rg * ghnb);
            float hp = hs[(nn + 16) * HS_STRIDE + j];
            float hn = (1.f - z) * nv + z * hp;
            hout[(long)nb * H_ + j] = hn;
            out[((long)t * N_ + nb) * OUTW_ + 2 + j] = hn;
        }

        // grid barrier (skip after the last step)
        if (t < T_ - 1) {
            __threadfence();
            __syncthreads();
            if (tid == 0) {
                unsigned target = (unsigned)(t + 1);
                unsigned prev = atomicAdd(&g_bar[0], 1u);
                if (prev == GRU_BLOCKS - 1) {
                    g_bar[0] = 0;
                    __threadfence();
                    atomicExch(&g_bar[1], target);
                } else {
                    while (atomicAdd(&g_bar[1], 0u) < target) __nanosleep(32);
                    __threadfence();
                }
            }
            __syncthreads();
        }
    }
}

// ---------------------------------------------------------------------------
__global__ __launch_bounds__(256) void epilogue_kernel(
    const float* __restrict__ WB, const float* __restrict__ CC,
    const int* __restrict__ actions, const float* __restrict__ Wc,
    const float* __restrict__ bc, float* __restrict__ out)
{
    long idx = blockIdx.x;          // t*N + n
    int t = (int)(idx / N_), n = (int)(idx % N_);
    int l = threadIdx.x;
    __shared__ float red[256];

    float w = WB[((long)n * T_ + t) * L_ + l] * CC[idx];
    red[l] = w;
    __syncthreads();
    for (int s = 128; s > 0; s >>= 1) {
        if (l < s) red[l] = fmaxf(red[l], red[l + s]);
        __syncthreads();
    }
    float mx = red[0];
    __syncthreads();
    float e = expf(w - mx);
    red[l] = e;
    __syncthreads();
    for (int s = 128; s > 0; s >>= 1) {
        if (l < s) red[l] += red[l + s];
        __syncthreads();
    }
    float sum = red[0];
    __syncthreads();

    long base = idx * OUTW_;
    out[base + 2 + 256 + l] = e / sum;
    int a = actions[idx];
    out[base + 2 + 512 + l] = (l == a) ? 1.f : 0.f;

    red[l] = out[base + 2 + l] * Wc[l];
    __syncthreads();
    for (int s = 128; s > 0; s >>= 1) {
        if (l < s) red[l] += red[l + s];
        __syncthreads();
    }
    if (l == 0) {
        out[base + 1] = red[0] + bc[0];
        out[base + 0] = (float)a;
    }
}

// ---------------------------------------------------------------------------
extern "C" void kernel_launch(void* const* d_in, const int* in_sizes, int n_in,
                              void* d_out, int out_size)
{
    const float* cond = (const float*)d_in[0];
    const float* M    = (const float*)d_in[1];
    const float* Km   = (const float*)d_in[2];
    const float* Cm   = (const float*)d_in[3];
    const float* h0   = (const float*)d_in[4];
    const float* p0   = (const float*)d_in[5];
    const float* W0   = (const float*)d_in[6];
    const float* b0   = (const float*)d_in[7];
    const float* W1   = (const float*)d_in[8];
    const float* b1   = (const float*)d_in[9];
    const float* W2   = (const float*)d_in[10];
    const float* b2   = (const float*)d_in[11];
    const float* W_ih = (const float*)d_in[12];
    const float* W_hh = (const float*)d_in[13];
    const float* b_ih = (const float*)d_in[14];
    const float* b_hh = (const float*)d_in[15];
    const float* Wa   = (const float*)d_in[16];
    const float* ba   = (const float*)d_in[17];
    const float* Wc   = (const float*)d_in[18];
    const float* bc   = (const float*)d_in[19];
    const int* actions = (const int*)d_in[20];
    float* out = (float*)d_out;

    float* base = nullptr;
    cudaGetSymbolAddress((void**)&base, g_scratch);
    float* XIN = base + XIN_OFF;
    float* XA  = base + XA_OFF;
    float* XB  = base + XB_OFF;
    float* GI  = base + GI_OFF;
    float* KB  = base + KB_OFF;
    float* WB  = base + WB_OFF;
    float* CC  = base + CC_OFF;
    float* HB  = base + HB_OFF;

    void* bar_addr = nullptr;
    cudaGetSymbolAddress(&bar_addr, g_bar);

    const int GRU_SMEM = 2 * 128 * 48 * 4 + 32 * HS_STRIDE * 4;  // 82432 B
    cudaFuncSetAttribute(gru_persistent,
                         cudaFuncAttributeMaxDynamicSharedMemorySize, GRU_SMEM);

    // phase A: inputs -> gi (fully parallel over T*N)
    t0_kernel<<<N_, 256>>>(p0, M, Cm, XIN, CC);
    gather_kernel<<<ROWS_, 256>>>(cond, M, Cm, actions, XIN, CC);
    gemm_kernel<false, true><<<dim3(ROWS_ / 64, 4, 1), 256>>>(
        XIN, W0, b0, XA, ROWS_, 256, 320, 320, 256, 256, 0, 0, 0);
    gemm_kernel<false, true><<<dim3(ROWS_ / 64, 4, 1), 256>>>(
        XA, W1, b1, XB, ROWS_, 256, 256, 256, 256, 256, 0, 0, 0);
    gemm_kernel<false, true><<<dim3(ROWS_ / 64, 4, 1), 256>>>(
        XB, W2, b2, XA, ROWS_, 256, 256, 256, 256, 256, 0, 0, 0);
    gemm_kernel<true, false><<<dim3(ROWS_ / 64, 12, 1), 256>>>(
        XA, W_ih, b_ih, GI, ROWS_, 768, 256, 256, 256, 768, 0, 0, 0);

    // phase B: persistent GRU (single kernel, internal grid barrier)
    cudaMemsetAsync(bar_addr, 0, 2 * sizeof(unsigned));
    gru_persistent<<<GRU_BLOCKS, 256, GRU_SMEM>>>(GI, HB, h0, W_hh, b_hh, out);

    // phase C: actor head (parallel again)
    gemm_kernel<false, false><<<dim3(ROWS_ / 64, 4, 1), 256>>>(
        out + 2, Wa, ba, KB, ROWS_, 256, 256, OUTW_, 256, 256, 0, 0, 0);
    gemm_kernel<true, false><<<dim3(2, 4, N_), 256>>>(
        KB, Km, nullptr, WB, T_, 256, 256, N_ * 256, 256, 256,
        256L, (long)L_ * H_, (long)T_ * L_);
    epilogue_kernel<<<ROWS_, 256>>>(WB, CC, actions, Wc, bc, out);
}

// round 3
// speedup vs baseline: 1.3942x; 1.2011x over previous
#include <cuda_runtime.h>
#include <math.h>

#define T_ 128
#define N_ 256
#define L_ 256
#define H_ 256
#define COND_ 64
#define ROWS_ (T_ * N_)   // 32768
#define OUTW_ 770         // 1 + 1 + H + L + L

// ---------------- scratch (single __device__ symbol, no allocations) -------
#define XIN_OFF 0L                                   // 320R, reused as HD (256R) later
#define XA_OFF  (XIN_OFF + (long)ROWS_ * 320)
#define XB_OFF  (XA_OFF  + (long)ROWS_ * 256)
#define GI_OFF  (XB_OFF  + (long)ROWS_ * 256)
#define KB_OFF  (GI_OFF  + (long)ROWS_ * 768)
#define WB_OFF  (KB_OFF  + (long)ROWS_ * 256)
#define CC_OFF  (WB_OFF  + (long)ROWS_ * 256)
#define HB_OFF  (CC_OFF  + (long)ROWS_)
#define SCRATCH_FLOATS (HB_OFF + 2L * N_ * H_)

__device__ float g_scratch[SCRATCH_FLOATS];
__device__ unsigned g_bar[2];   // [0]=monotonic arrive counter, [1]=epoch

// ---------------- packed fp32x2 helpers (sm_103a) ---------------------------
#define FMA2(d, a, b) \
    asm("fma.rn.f32x2 %0, %1, %2, %0;" : "+l"(d) : "l"(a), "l"(b))
#define DUP2(d, x) \
    asm("mov.b64 %0, {%1, %1};" : "=l"(d) : "f"(x))
#define UNPACK2(lo, hi, v) \
    asm("mov.b64 {%0, %1}, %2;" : "=f"(lo), "=f"(hi) : "l"(v))

// ---------------------------------------------------------------------------
__global__ __launch_bounds__(256) void t0_kernel(
    const float* __restrict__ p0, const float* __restrict__ M,
    const float* __restrict__ C, float* __restrict__ XIN, float* __restrict__ CC)
{
    int n = blockIdx.x;
    int tid = threadIdx.x;
    __shared__ float red[256];
    __shared__ float ps[256];

    float v = p0[(long)n * L_ + tid];
    red[tid] = (v != 0.f) ? 1.f : 0.f;
    __syncthreads();
    for (int s = 128; s > 0; s >>= 1) {
        if (tid < s) red[tid] += red[tid + s];
        __syncthreads();
    }
    bool any = red[0] > 0.f;
    float pl = v;
    if (tid == 0 && !any) pl = 1.f;
    ps[tid] = pl;
    __syncthreads();

    float acc = 0.f;
    const float* Mn = M + (long)n * L_ * H_;
    for (int l = 0; l < L_; l++)
        acc = fmaf(ps[l], Mn[(long)l * H_ + tid], acc);
    XIN[(long)n * 320 + 64 + tid] = acc;

    red[tid] = ps[tid] * C[(long)n * L_ + tid];
    __syncthreads();
    for (int s = 128; s > 0; s >>= 1) {
        if (tid < s) red[tid] += red[tid + s];
        __syncthreads();
    }
    if (tid == 0) CC[n] = red[0];
}

// ---------------------------------------------------------------------------
__global__ __launch_bounds__(256) void gather_kernel(
    const float* __restrict__ cond, const float* __restrict__ M,
    const float* __restrict__ C, const int* __restrict__ actions,
    float* __restrict__ XIN, float* __restrict__ CC)
{
    long idx = blockIdx.x;          // t*N + n
    int t = (int)(idx / N_), n = (int)(idx % N_);
    int tid = threadIdx.x;
    float* xrow = XIN + idx * 320;
    if (tid < 64) xrow[tid] = cond[idx * COND_ + tid];
    if (t > 0) {
        int a = actions[idx - N_];  // actions[t-1, n]
        xrow[64 + tid] = M[((long)n * L_ + a) * H_ + tid];
        if (tid == 0) CC[idx] = C[(long)n * L_ + a];
    }
}

// ---------------------------------------------------------------------------
// fp32 GEMM, 128x128 block tile, 8x8 per thread, f32x2 accumulators.
// All M,N multiples of 128 here; K multiple of 16; A,B,C 16B-aligned,
// lda/ldb/ldc multiples of 4.
template <bool TRANSB, bool RELU>
__global__ __launch_bounds__(256) void gemm_kernel(
    const float* __restrict__ A, const float* __restrict__ B,
    const float* __restrict__ bias, float* __restrict__ C,
    int M, int N, int K, int lda, int ldb, int ldc,
    long batchA, long batchB, long batchC)
{
    constexpr int BM = 128, BN = 128, BK = 16;
    __shared__ float As[BK][BM + 4];
    __shared__ float Bs[BK][BN + 4];

    long bz = blockIdx.z;
    A += bz * batchA; B += bz * batchB; C += bz * batchC;
    int m0 = blockIdx.x * BM, n0 = blockIdx.y * BN;
    int tid = threadIdx.x;
    int tx = tid & 15, ty = tid >> 4;   // 16 x 16 thread grid, 8x8 each

    unsigned long long acc[8][4];
#pragma unroll
    for (int i = 0; i < 8; i++)
#pragma unroll
        for (int j = 0; j < 4; j++) acc[i][j] = 0ull;

    for (int k0 = 0; k0 < K; k0 += BK) {
        // A tile: 128m x 16k, transposed into As[k][m]
#pragma unroll
        for (int i = 0; i < 2; i++) {
            int idx = tid + i * 256;        // 0..511
            int m = idx & 127;
            int c = idx >> 7;               // 0..3 (k-chunk of 4)
            float4 v = *(const float4*)&A[(long)(m0 + m) * lda + k0 + c * 4];
            As[c * 4 + 0][m] = v.x;
            As[c * 4 + 1][m] = v.y;
            As[c * 4 + 2][m] = v.z;
            As[c * 4 + 3][m] = v.w;
        }
        if (!TRANSB) {
#pragma unroll
            for (int i = 0; i < 2; i++) {
                int idx = tid + i * 256;    // 16k x 32 float4
                int k = idx >> 5;
                int n4 = idx & 31;
                float4 v = *(const float4*)&B[(long)(k0 + k) * ldb + n0 + n4 * 4];
                *(float4*)&Bs[k][n4 * 4] = v;
            }
        } else {
#pragma unroll
            for (int i = 0; i < 2; i++) {
                int idx = tid + i * 256;
                int n = idx & 127;
                int c = idx >> 7;
                float4 v = *(const float4*)&B[(long)(n0 + n) * ldb + k0 + c * 4];
                Bs[c * 4 + 0][n] = v.x;
                Bs[c * 4 + 1][n] = v.y;
                Bs[c * 4 + 2][n] = v.z;
                Bs[c * 4 + 3][n] = v.w;
            }
        }
        __syncthreads();
#pragma unroll
        for (int k = 0; k < BK; k++) {
            float a[8];
            *(float4*)&a[0] = *(float4*)&As[k][ty * 8];
            *(float4*)&a[4] = *(float4*)&As[k][ty * 8 + 4];
            const unsigned long long* bp =
                (const unsigned long long*)&Bs[k][tx * 8];
            unsigned long long b0 = bp[0], b1 = bp[1], b2 = bp[2], b3 = bp[3];
#pragma unroll
            for (int i = 0; i < 8; i++) {
                unsigned long long ad;
                DUP2(ad, a[i]);
                FMA2(acc[i][0], ad, b0);
                FMA2(acc[i][1], ad, b1);
                FMA2(acc[i][2], ad, b2);
                FMA2(acc[i][3], ad, b3);
            }
        }
        __syncthreads();
    }

    float bias0[8];
    if (bias) {
        *(float4*)&bias0[0] = *(const float4*)&bias[n0 + tx * 8];
        *(float4*)&bias0[4] = *(const float4*)&bias[n0 + tx * 8 + 4];
    }
#pragma unroll
    for (int i = 0; i < 8; i++) {
        int m = m0 + ty * 8 + i;
        float v[8];
#pragma unroll
        for (int j = 0; j < 4; j++) UNPACK2(v[2 * j], v[2 * j + 1], acc[i][j]);
        if (bias) {
#pragma unroll
            for (int j = 0; j < 8; j++) v[j] += bias0[j];
        }
        if (RELU) {
#pragma unroll
            for (int j = 0; j < 8; j++) v[j] = fmaxf(v[j], 0.f);
        }
        float* cp = &C[(long)m * ldc + n0 + tx * 8];
        *(float4*)&cp[0] = *(float4*)&v[0];
        *(float4*)&cp[4] = *(float4*)&v[4];
    }
}

// ---------------------------------------------------------------------------
// persistent GRU: 128 blocks (16 j-tiles x 8 n-tiles), W_hh slice cached in
// smem once (k-transposed, f32x2-packed), 128 timesteps with fast grid barrier.
#define GRU_BLOCKS 128
#define HS_STRIDE 260

__device__ __forceinline__ float sigmf(float x) { return 1.f / (1.f + expf(-x)); }

__global__ __launch_bounds__(256) void gru_persistent(
    const float* __restrict__ GI, float* __restrict__ HB,
    const float* __restrict__ h0, const float* __restrict__ W_hh,
    const float* __restrict__ b_hh, float* __restrict__ out,
    float* __restrict__ HD)
{
    extern __shared__ float smem[];
    float2* wp = (float2*)smem;                 // [128 kpairs][48 rows]
    float* hs = smem + 2 * 128 * 48;            // [32][HS_STRIDE]

    int tid = threadIdx.x;
    int jt = blockIdx.x & 15, nt = blockIdx.x >> 4;
    int j0 = jt * 16, n0 = nt * 32;
    int jj = tid & 15, nn = tid >> 4;
    int j = j0 + jj;
    int na = n0 + nn, nb = n0 + nn + 16;

    // load W slice once: wp[kp][g*16+jr] = (W_hh[g*256+j0+jr][2kp], [2kp+1])
    for (int e = tid; e < 48 * 64; e += 256) {
        int r = e >> 6;          // 0..47
        int c = e & 63;          // float4 chunk over k
        int g = r >> 4, jr = r & 15;
        float4 v = *(const float4*)&W_hh[(long)(g * 256 + j0 + jr) * 256 + c * 4];
        wp[(2 * c + 0) * 48 + r] = make_float2(v.x, v.y);
        wp[(2 * c + 1) * 48 + r] = make_float2(v.z, v.w);
    }
    float bhr = b_hh[j], bhz = b_hh[256 + j], bhn = b_hh[512 + j];

    // prefetch gi(0)
    const float* gia = GI + (long)na * 768;
    const float* gib = GI + (long)nb * 768;
    float gra = gia[j], gza = gia[256 + j], gna = gia[512 + j];
    float grb = gib[j], gzb = gib[256 + j], gnb = gib[512 + j];

    for (int t = 0; t < T_; t++) {
        const float* hin = (t == 0) ? h0 : (HB + ((t & 1) ^ 1) * (N_ * H_));
        float* hout = HB + (t & 1) * (N_ * H_);

        // load h tile [n0..n0+32) x 256 into smem (coalesced float4)
        {
            int n = tid >> 3, f = tid & 7;
            const float* src = hin + (long)(n0 + n) * H_;
            float* dst = hs + n * HS_STRIDE;
#pragma unroll
            for (int i = 0; i < 8; i++) {
                int c = (f + i * 8) * 4;
                *(float4*)&dst[c] = *(const float4*)&src[c];
            }
        }
        __syncthreads();

        unsigned long long a0 = 0, a1 = 0, a2 = 0, b0 = 0, b1 = 0, b2 = 0;
        const unsigned long long* ha =
            (const unsigned long long*)(hs + nn * HS_STRIDE);
        const unsigned long long* hbp =
            (const unsigned long long*)(hs + (nn + 16) * HS_STRIDE);
#pragma unroll 4
        for (int kp = 0; kp < 128; kp++) {
            unsigned long long hva = ha[kp];
            unsigned long long hvb = hbp[kp];
            const unsigned long long* w =
                (const unsigned long long*)(wp + kp * 48);
            unsigned long long w0 = w[jj], w1 = w[16 + jj], w2 = w[32 + jj];
            FMA2(a0, hva, w0); FMA2(a1, hva, w1); FMA2(a2, hva, w2);
            FMA2(b0, hvb, w0); FMA2(b1, hvb, w1); FMA2(b2, hvb, w2);
        }
        float lo, hi;
        UNPACK2(lo, hi, a0); float ghra = lo + hi + bhr;
        UNPACK2(lo, hi, a1); float ghza = lo + hi + bhz;
        UNPACK2(lo, hi, a2); float ghna = lo + hi + bhn;
        UNPACK2(lo, hi, b0); float ghrb = lo + hi + bhr;
        UNPACK2(lo, hi, b1); float ghzb = lo + hi + bhz;
        UNPACK2(lo, hi, b2); float ghnb = lo + hi + bhn;

        {
            float rg = sigmf(gra + ghra);
            float z  = sigmf(gza + ghza);
            float nv = tanhf(gna + rg * ghna);
            float hp = hs[nn * HS_STRIDE + j];
            float hn = (1.f - z) * nv + z * hp;
            hout[(long)na * H_ + j] = hn;
            out[((long)t * N_ + na) * OUTW_ + 2 + j] = hn;
            HD[((long)t * N_ + na) * 256 + j] = hn;
        }
        {
            float rg = sigmf(grb + ghrb);
            float z  = sigmf(gzb + ghzb);
            float nv = tanhf(gnb + rg * ghnb);
            float hp = hs[(nn + 16) * HS_STRIDE + j];
            float hn = (1.f - z) * nv + z * hp;
            hout[(long)nb * H_ + j] = hn;
            out[((long)t * N_ + nb) * OUTW_ + 2 + j] = hn;
            HD[((long)t * N_ + nb) * 256 + j] = hn;
        }

        if (t < T_ - 1) {
            // arrive (release): one fence + one atomic per block
            __syncthreads();
            if (tid == 0) {
                __threadfence();
                unsigned prev = atomicAdd(&g_bar[0], 1u);
                if (prev == (unsigned)(t + 1) * GRU_BLOCKS - 1u) {
                    asm volatile("st.release.gpu.global.u32 [%0], %1;"
                                 :: "l"(&g_bar[1]), "r"((unsigned)(t + 1))
                                 : "memory");
                }
            }
            // prefetch gi(t+1) while waiting (independent of h)
            gia = GI + ((long)(t + 1) * N_ + na) * 768;
            gib = GI + ((long)(t + 1) * N_ + nb) * 768;
            gra = gia[j]; gza = gia[256 + j]; gna = gia[512 + j];
            grb = gib[j]; gzb = gib[256 + j]; gnb = gib[512 + j];
            // wait: plain acquire loads (no RMW contention)
            if (tid == 0) {
                unsigned e;
                do {
                    asm volatile("ld.acquire.gpu.global.u32 %0, [%1];"
                                 : "=r"(e) : "l"(&g_bar[1]) : "memory");
                } while (e < (unsigned)(t + 1));
            }
            __syncthreads();
        }
    }
}

// ---------------------------------------------------------------------------
__global__ __launch_bounds__(256) void epilogue_kernel(
    const float* __restrict__ WB, const float* __restrict__ CC,
    const int* __restrict__ actions, const float* __restrict__ Wc,
    const float* __restrict__ bc, const float* __restrict__ HD,
    float* __restrict__ out)
{
    long idx = blockIdx.x;          // t*N + n
    int t = (int)(idx / N_), n = (int)(idx % N_);
    int l = threadIdx.x;
    __shared__ float red[256];

    float w = WB[((long)n * T_ + t) * L_ + l] * CC[idx];
    red[l] = w;
    __syncthreads();
    for (int s = 128; s > 0; s >>= 1) {
        if (l < s) red[l] = fmaxf(red[l], red[l + s]);
        __syncthreads();
    }
    float mx = red[0];
    __syncthreads();
    float e = expf(w - mx);
    red[l] = e;
    __syncthreads();
    for (int s = 128; s > 0; s >>= 1) {
        if (l < s) red[l] += red[l + s];
        __syncthreads();
    }
    float sum = red[0];
    __syncthreads();

    long base = idx * OUTW_;
    out[base + 2 + 256 + l] = e / sum;
    int a = actions[idx];
    out[base + 2 + 512 + l] = (l == a) ? 1.f : 0.f;

    red[l] = HD[idx * 256 + l] * Wc[l];
    __syncthreads();
    for (int s = 128; s > 0; s >>= 1) {
        if (l < s) red[l] += red[l + s];
        __syncthreads();
    }
    if (l == 0) {
        out[base + 1] = red[0] + bc[0];
        out[base + 0] = (float)a;
    }
}

// ---------------------------------------------------------------------------
extern "C" void kernel_launch(void* const* d_in, const int* in_sizes, int n_in,
                              void* d_out, int out_size)
{
    const float* cond = (const float*)d_in[0];
    const float* M    = (const float*)d_in[1];
    const float* Km   = (const float*)d_in[2];
    const float* Cm   = (const float*)d_in[3];
    const float* h0   = (const float*)d_in[4];
    const float* p0   = (const float*)d_in[5];
    const float* W0   = (const float*)d_in[6];
    const float* b0   = (const float*)d_in[7];
    const float* W1   = (const float*)d_in[8];
    const float* b1   = (const float*)d_in[9];
    const float* W2   = (const float*)d_in[10];
    const float* b2   = (const float*)d_in[11];
    const float* W_ih = (const float*)d_in[12];
    const float* W_hh = (const float*)d_in[13];
    const float* b_ih = (const float*)d_in[14];
    const float* b_hh = (const float*)d_in[15];
    const float* Wa   = (const float*)d_in[16];
    const float* ba   = (const float*)d_in[17];
    const float* Wc   = (const float*)d_in[18];
    const float* bc   = (const float*)d_in[19];
    const int* actions = (const int*)d_in[20];
    float* out = (float*)d_out;

    float* base = nullptr;
    cudaGetSymbolAddress((void**)&base, g_scratch);
    float* XIN = base + XIN_OFF;
    float* XA  = base + XA_OFF;
    float* XB  = base + XB_OFF;
    float* GI  = base + GI_OFF;
    float* KB  = base + KB_OFF;
    float* WB  = base + WB_OFF;
    float* CC  = base + CC_OFF;
    float* HB  = base + HB_OFF;
    float* HD  = base + XIN_OFF;   // reuse XIN region after phase A

    void* bar_addr = nullptr;
    cudaGetSymbolAddress(&bar_addr, g_bar);

    const int GRU_SMEM = 2 * 128 * 48 * 4 + 32 * HS_STRIDE * 4;  // 82432 B
    cudaFuncSetAttribute(gru_persistent,
                         cudaFuncAttributeMaxDynamicSharedMemorySize, GRU_SMEM);

    // phase A: inputs -> gi (fully parallel over T*N)
    t0_kernel<<<N_, 256>>>(p0, M, Cm, XIN, CC);
    gather_kernel<<<ROWS_, 256>>>(cond, M, Cm, actions, XIN, CC);
    gemm_kernel<false, true><<<dim3(ROWS_ / 128, 2, 1), 256>>>(
        XIN, W0, b0, XA, ROWS_, 256, 320, 320, 256, 256, 0, 0, 0);
    gemm_kernel<false, true><<<dim3(ROWS_ / 128, 2, 1), 256>>>(
        XA, W1, b1, XB, ROWS_, 256, 256, 256, 256, 256, 0, 0, 0);
    gemm_kernel<false, true><<<dim3(ROWS_ / 128, 2, 1), 256>>>(
        XB, W2, b2, XA, ROWS_, 256, 256, 256, 256, 256, 0, 0, 0);
    gemm_kernel<true, false><<<dim3(ROWS_ / 128, 6, 1), 256>>>(
        XA, W_ih, b_ih, GI, ROWS_, 768, 256, 256, 256, 768, 0, 0, 0);

    // phase B: persistent GRU (single kernel, internal grid barrier)
    cudaMemsetAsync(bar_addr, 0, 2 * sizeof(unsigned));
    gru_persistent<<<GRU_BLOCKS, 256, GRU_SMEM>>>(GI, HB, h0, W_hh, b_hh, out, HD);

    // phase C: actor head (parallel again)
    gemm_kernel<false, false><<<dim3(ROWS_ / 128, 2, 1), 256>>>(
        HD, Wa, ba, KB, ROWS_, 256, 256, 256, 256, 256, 0, 0, 0);
    gemm_kernel<true, false><<<dim3(1, 2, N_), 256>>>(
        KB, Km, nullptr, WB, T_, 256, 256, N_ * 256, 256, 256,
        256L, (long)L_ * H_, (long)T_ * L_);
    epilogue_kernel<<<ROWS_, 256>>>(WB, CC, actions, Wc, bc, HD, out);
}

// round 4
// speedup vs baseline: 1.4551x; 1.0437x over previous
#include <cuda_runtime.h>
#include <math.h>

#define T_ 128
#define N_ 256
#define L_ 256
#define H_ 256
#define COND_ 64
#define ROWS_ (T_ * N_)   // 32768
#define OUTW_ 770         // 1 + 1 + H + L + L

// ---------------- scratch (single __device__ symbol, no allocations) -------
#define XIN_OFF 0L                                   // 320R, reused as HD (256R) later
#define XA_OFF  (XIN_OFF + (long)ROWS_ * 320)
#define XB_OFF  (XA_OFF  + (long)ROWS_ * 256)
#define GI_OFF  (XB_OFF  + (long)ROWS_ * 256)
#define KB_OFF  (GI_OFF  + (long)ROWS_ * 768)
#define WB_OFF  (KB_OFF  + (long)ROWS_ * 256)
#define CC_OFF  (WB_OFF  + (long)ROWS_ * 256)
#define HB_OFF  (CC_OFF  + (long)ROWS_)
#define SCRATCH_FLOATS (HB_OFF + 2L * N_ * H_)

__device__ float g_scratch[SCRATCH_FLOATS];
// per-group barriers: groups g=0..7; arrive at [g*32], epoch at [(8+g)*32]
__device__ unsigned g_bar2[16 * 32];

// ---------------- packed fp32x2 helpers (sm_103a) ---------------------------
#define FMA2(d, a, b) \
    asm("fma.rn.f32x2 %0, %1, %2, %0;" : "+l"(d) : "l"(a), "l"(b))
#define DUP2(d, x) \
    asm("mov.b64 %0, {%1, %1};" : "=l"(d) : "f"(x))
#define UNPACK2(lo, hi, v) \
    asm("mov.b64 {%0, %1}, %2;" : "=f"(lo), "=f"(hi) : "l"(v))

// ---------------------------------------------------------------------------
// t=0: p_init handling. Fast path: p0 row all-zero -> r0 = M[n,0,:], cc=C[n,0]
__global__ __launch_bounds__(256) void t0_kernel(
    const float* __restrict__ p0, const float* __restrict__ M,
    const float* __restrict__ C, float* __restrict__ XIN, float* __restrict__ CC)
{
    int n = blockIdx.x;
    int tid = threadIdx.x;
    float v = p0[(long)n * L_ + tid];
    int any = __syncthreads_or(v != 0.f);
    if (!any) {
        XIN[(long)n * 320 + 64 + tid] = M[(long)n * L_ * H_ + tid];
        if (tid == 0) CC[n] = C[(long)n * L_];
        return;
    }
    // generic slow path (p0 has nonzero rows)
    __shared__ float red[256];
    __shared__ float ps[256];
    ps[tid] = v;
    __syncthreads();
    float acc = 0.f;
    const float* Mn = M + (long)n * L_ * H_;
    for (int l = 0; l < L_; l++)
        acc = fmaf(ps[l], Mn[(long)l * H_ + tid], acc);
    XIN[(long)n * 320 + 64 + tid] = acc;
    red[tid] = ps[tid] * C[(long)n * L_ + tid];
    __syncthreads();
    for (int s = 128; s > 0; s >>= 1) {
        if (tid < s) red[tid] += red[tid + s];
        __syncthreads();
    }
    if (tid == 0) CC[n] = red[0];
}

// ---------------------------------------------------------------------------
// builds XIN rows [cond(64) | r(256)] and CC, 8 rows per block, float4 moves
__global__ __launch_bounds__(256) void gather_kernel(
    const float* __restrict__ cond, const float* __restrict__ M,
    const float* __restrict__ C, const int* __restrict__ actions,
    float* __restrict__ XIN, float* __restrict__ CC)
{
    int r = threadIdx.x >> 5, lane = threadIdx.x & 31;
    long idx = (long)blockIdx.x * 8 + r;    // t*N + n
    int t = (int)(idx / N_), n = (int)(idx % N_);
    float4* dst = (float4*)(XIN + idx * 320);
    const float4* csrc = (const float4*)(cond + idx * COND_);
    if (lane < 16) dst[lane] = csrc[lane];
    if (t > 0) {
        int a = actions[idx - N_];          // actions[t-1, n]
        const float4* msrc = (const float4*)(M + ((long)n * L_ + a) * H_);
#pragma unroll
        for (int i = 0; i < 2; i++) dst[16 + lane + i * 32] = msrc[lane + i * 32];
        if (lane == 0) CC[idx] = C[(long)n * L_ + a];
    }
}

// ---------------------------------------------------------------------------
// fp32 GEMM, 128x128 tile, 8x8/thread, f32x2 accumulators, double-buffered.
template <bool TRANSB, bool RELU>
__global__ __launch_bounds__(256, 2) void gemm_kernel(
    const float* __restrict__ A, const float* __restrict__ B,
    const float* __restrict__ bias, float* __restrict__ C,
    int M, int N, int K, int lda, int ldb, int ldc,
    long batchA, long batchB, long batchC)
{
    constexpr int BM = 128, BN = 128, BK = 16;
    __shared__ float As[2][BK][BM + 4];
    __shared__ float Bs[2][BK][BN + 4];

    long bz = blockIdx.z;
    A += bz * batchA; B += bz * batchB; C += bz * batchC;
    int m0 = blockIdx.x * BM, n0 = blockIdx.y * BN;
    int tid = threadIdx.x;
    int tx = tid & 15, ty = tid >> 4;

    // load coordinates (two elements per thread per operand)
    int am[2], ac[2], bk_[2], bn4[2], bn[2], bc[2];
#pragma unroll
    for (int i = 0; i < 2; i++) {
        int idx = tid + i * 256;
        am[i] = idx & 127; ac[i] = idx >> 7;          // A: (m, k-chunk)
        bk_[i] = idx >> 5; bn4[i] = idx & 31;         // B row-major: (k, n4)
        bn[i] = idx & 127; bc[i] = idx >> 7;          // B transposed: (n, k-chunk)
    }

    unsigned long long acc[8][4];
#pragma unroll
    for (int i = 0; i < 8; i++)
#pragma unroll
        for (int j = 0; j < 4; j++) acc[i][j] = 0ull;

    // prologue: stage 0
#pragma unroll
    for (int i = 0; i < 2; i++) {
        float4 v = *(const float4*)&A[(long)(m0 + am[i]) * lda + ac[i] * 4];
        As[0][ac[i] * 4 + 0][am[i]] = v.x;
        As[0][ac[i] * 4 + 1][am[i]] = v.y;
        As[0][ac[i] * 4 + 2][am[i]] = v.z;
        As[0][ac[i] * 4 + 3][am[i]] = v.w;
        if (!TRANSB) {
            float4 b = *(const float4*)&B[(long)bk_[i] * ldb + n0 + bn4[i] * 4];
            *(float4*)&Bs[0][bk_[i]][bn4[i] * 4] = b;
        } else {
            float4 b = *(const float4*)&B[(long)(n0 + bn[i]) * ldb + bc[i] * 4];
            Bs[0][bc[i] * 4 + 0][bn[i]] = b.x;
            Bs[0][bc[i] * 4 + 1][bn[i]] = b.y;
            Bs[0][bc[i] * 4 + 2][bn[i]] = b.z;
            Bs[0][bc[i] * 4 + 3][bn[i]] = b.w;
        }
    }
    __syncthreads();

    int nk = K / BK;
    float4 ra[2], rb[2];
    for (int it = 0; it < nk; it++) {
        int buf = it & 1;
        bool has_next = (it + 1 < nk);
        if (has_next) {
            int k0 = (it + 1) * BK;
#pragma unroll
            for (int i = 0; i < 2; i++) {
                ra[i] = *(const float4*)&A[(long)(m0 + am[i]) * lda + k0 + ac[i] * 4];
                if (!TRANSB)
                    rb[i] = *(const float4*)&B[(long)(k0 + bk_[i]) * ldb + n0 + bn4[i] * 4];
                else
                    rb[i] = *(const float4*)&B[(long)(n0 + bn[i]) * ldb + k0 + bc[i] * 4];
            }
        }
#pragma unroll
        for (int k = 0; k < BK; k++) {
            float a[8];
            *(float4*)&a[0] = *(float4*)&As[buf][k][ty * 8];
            *(float4*)&a[4] = *(float4*)&As[buf][k][ty * 8 + 4];
            const unsigned long long* bp =
                (const unsigned long long*)&Bs[buf][k][tx * 8];
            unsigned long long b0 = bp[0], b1 = bp[1], b2 = bp[2], b3 = bp[3];
#pragma unroll
            for (int i = 0; i < 8; i++) {
                unsigned long long ad;
                DUP2(ad, a[i]);
                FMA2(acc[i][0], ad, b0);
                FMA2(acc[i][1], ad, b1);
                FMA2(acc[i][2], ad, b2);
                FMA2(acc[i][3], ad, b3);
            }
        }
        if (has_next) {
            int nb = buf ^ 1;
#pragma unroll
            for (int i = 0; i < 2; i++) {
                As[nb][ac[i] * 4 + 0][am[i]] = ra[i].x;
                As[nb][ac[i] * 4 + 1][am[i]] = ra[i].y;
                As[nb][ac[i] * 4 + 2][am[i]] = ra[i].z;
                As[nb][ac[i] * 4 + 3][am[i]] = ra[i].w;
                if (!TRANSB) {
                    *(float4*)&Bs[nb][bk_[i]][bn4[i] * 4] = rb[i];
                } else {
                    Bs[nb][bc[i] * 4 + 0][bn[i]] = rb[i].x;
                    Bs[nb][bc[i] * 4 + 1][bn[i]] = rb[i].y;
                    Bs[nb][bc[i] * 4 + 2][bn[i]] = rb[i].z;
                    Bs[nb][bc[i] * 4 + 3][bn[i]] = rb[i].w;
                }
            }
        }
        __syncthreads();
    }

    float bias0[8];
    if (bias) {
        *(float4*)&bias0[0] = *(const float4*)&bias[n0 + tx * 8];
        *(float4*)&bias0[4] = *(const float4*)&bias[n0 + tx * 8 + 4];
    }
#pragma unroll
    for (int i = 0; i < 8; i++) {
        int m = m0 + ty * 8 + i;
        float v[8];
#pragma unroll
        for (int j = 0; j < 4; j++) UNPACK2(v[2 * j], v[2 * j + 1], acc[i][j]);
        if (bias) {
#pragma unroll
            for (int j = 0; j < 8; j++) v[j] += bias0[j];
        }
        if (RELU) {
#pragma unroll
            for (int j = 0; j < 8; j++) v[j] = fmaxf(v[j], 0.f);
        }
        float* cp = &C[(long)m * ldc + n0 + tx * 8];
        *(float4*)&cp[0] = *(float4*)&v[0];
        *(float4*)&cp[4] = *(float4*)&v[4];
    }
}

// ---------------------------------------------------------------------------
// persistent GRU: 128 blocks (16 jt x 8 nt). h exchange only couples blocks
// with the same nt -> per-group 16-block barrier (8 independent barriers).
#define GRU_BLOCKS 128
#define HS_STRIDE 260

__device__ __forceinline__ float sigmf(float x) { return 1.f / (1.f + expf(-x)); }

__global__ __launch_bounds__(256) void gru_persistent(
    const float* __restrict__ GI, float* __restrict__ HB,
    const float* __restrict__ h0, const float* __restrict__ W_hh,
    const float* __restrict__ b_hh, float* __restrict__ out,
    float* __restrict__ HD)
{
    extern __shared__ float smem[];
    float2* wp = (float2*)smem;                 // [128 kpairs][48 rows]
    float* hs = smem + 2 * 128 * 48;            // [32][HS_STRIDE]

    int tid = threadIdx.x;
    int jt = blockIdx.x & 15, nt = blockIdx.x >> 4;
    int j0 = jt * 16, n0 = nt * 32;
    int jj = tid & 15, nn = tid >> 4;
    int j = j0 + jj;
    int na = n0 + nn, nb = n0 + nn + 16;

    unsigned* arr = &g_bar2[nt * 32];
    unsigned* ep  = &g_bar2[(8 + nt) * 32];

    // load W slice once: wp[kp][g*16+jr] = (W_hh[g*256+j0+jr][2kp], [2kp+1])
    for (int e = tid; e < 48 * 64; e += 256) {
        int r = e >> 6;          // 0..47
        int c = e & 63;          // float4 chunk over k
        int g = r >> 4, jr = r & 15;
        float4 v = *(const float4*)&W_hh[(long)(g * 256 + j0 + jr) * 256 + c * 4];
        wp[(2 * c + 0) * 48 + r] = make_float2(v.x, v.y);
        wp[(2 * c + 1) * 48 + r] = make_float2(v.z, v.w);
    }
    float bhr = b_hh[j], bhz = b_hh[256 + j], bhn = b_hh[512 + j];

    // prefetch gi(0)
    const float* gia = GI + (long)na * 768;
    const float* gib = GI + (long)nb * 768;
    float gra = gia[j], gza = gia[256 + j], gna = gia[512 + j];
    float grb = gib[j], gzb = gib[256 + j], gnb = gib[512 + j];

    for (int t = 0; t < T_; t++) {
        const float* hin = (t == 0) ? h0 : (HB + ((t & 1) ^ 1) * (N_ * H_));
        float* hout = HB + (t & 1) * (N_ * H_);

        // load h tile [n0..n0+32) x 256 into smem (coalesced float4)
        {
            int n = tid >> 3, f = tid & 7;
            const float* src = hin + (long)(n0 + n) * H_;
            float* dst = hs + n * HS_STRIDE;
#pragma unroll
            for (int i = 0; i < 8; i++) {
                int c = (f + i * 8) * 4;
                *(float4*)&dst[c] = *(const float4*)&src[c];
            }
        }
        __syncthreads();

        unsigned long long a0 = 0, a1 = 0, a2 = 0, b0 = 0, b1 = 0, b2 = 0;
        const unsigned long long* ha =
            (const unsigned long long*)(hs + nn * HS_STRIDE);
        const unsigned long long* hbp =
            (const unsigned long long*)(hs + (nn + 16) * HS_STRIDE);
#pragma unroll 4
        for (int kp = 0; kp < 128; kp++) {
            unsigned long long hva = ha[kp];
            unsigned long long hvb = hbp[kp];
            const unsigned long long* w =
                (const unsigned long long*)(wp + kp * 48);
            unsigned long long w0 = w[jj], w1 = w[16 + jj], w2 = w[32 + jj];
            FMA2(a0, hva, w0); FMA2(a1, hva, w1); FMA2(a2, hva, w2);
            FMA2(b0, hvb, w0); FMA2(b1, hvb, w1); FMA2(b2, hvb, w2);
        }
        float lo, hi;
        UNPACK2(lo, hi, a0); float ghra = lo + hi + bhr;
        UNPACK2(lo, hi, a1); float ghza = lo + hi + bhz;
        UNPACK2(lo, hi, a2); float ghna = lo + hi + bhn;
        UNPACK2(lo, hi, b0); float ghrb = lo + hi + bhr;
        UNPACK2(lo, hi, b1); float ghzb = lo + hi + bhz;
        UNPACK2(lo, hi, b2); float ghnb = lo + hi + bhn;

        float hna, hnb2;
        {
            float rg = sigmf(gra + ghra);
            float z  = sigmf(gza + ghza);
            float nv = tanhf(gna + rg * ghna);
            float hp = hs[nn * HS_STRIDE + j];
            hna = (1.f - z) * nv + z * hp;
        }
        {
            float rg = sigmf(grb + ghrb);
            float z  = sigmf(gzb + ghzb);
            float nv = tanhf(gnb + rg * ghnb);
            float hp = hs[(nn + 16) * HS_STRIDE + j];
            hnb2 = (1.f - z) * nv + z * hp;
        }
        hout[(long)na * H_ + j] = hna;
        hout[(long)nb * H_ + j] = hnb2;

        if (t < T_ - 1) {
            __syncthreads();                 // all h stores issued
            if (tid == 0) {
                unsigned prev;
                asm volatile("atom.release.gpu.global.add.u32 %0, [%1], %2;"
                             : "=r"(prev) : "l"(arr), "r"(1u) : "memory");
                if (prev == (unsigned)((t + 1) * 16 - 1)) {
                    asm volatile("st.release.gpu.global.u32 [%0], %1;"
                                 :: "l"(ep), "r"((unsigned)(t + 1)) : "memory");
                }
            }
        }

        // non-exchanged stores off the critical path
        out[((long)t * N_ + na) * OUTW_ + 2 + j] = hna;
        out[((long)t * N_ + nb) * OUTW_ + 2 + j] = hnb2;
        HD[((long)t * N_ + na) * 256 + j] = hna;
        HD[((long)t * N_ + nb) * 256 + j] = hnb2;

        if (t < T_ - 1) {
            // prefetch gi(t+1) while waiting
            gia = GI + ((long)(t + 1) * N_ + na) * 768;
            gib = GI + ((long)(t + 1) * N_ + nb) * 768;
            gra = gia[j]; gza = gia[256 + j]; gna = gia[512 + j];
            grb = gib[j]; gzb = gib[256 + j]; gnb = gib[512 + j];
            if (tid == 0) {
                unsigned e;
                do {
                    asm volatile("ld.acquire.gpu.global.u32 %0, [%1];"
                                 : "=r"(e) : "l"(ep) : "memory");
                } while (e < (unsigned)(t + 1));
            }
            __syncthreads();
        }
    }
}

// ---------------------------------------------------------------------------
// warp-per-(t,n) epilogue: softmax(w*cc), one-hot, action, value. No smem.
__global__ __launch_bounds__(256) void epilogue_kernel(
    const float* __restrict__ WB, const float* __restrict__ CC,
    const int* __restrict__ actions, const float* __restrict__ Wc,
    const float* __restrict__ bc, const float* __restrict__ HD,
    float* __restrict__ out)
{
    int wid = threadIdx.x >> 5, lane = threadIdx.x & 31;
    long idx = (long)blockIdx.x * 8 + wid;   // t*N + n
    int t = (int)(idx / N_), n = (int)(idx % N_);
    float cc = CC[idx];
    long base = idx * OUTW_;

    const float4* wrow = (const float4*)(WB + ((long)n * T_ + t) * L_);
    float4 w0 = wrow[lane * 2], w1 = wrow[lane * 2 + 1];
    float wv[8] = {w0.x * cc, w0.y * cc, w0.z * cc, w0.w * cc,
                   w1.x * cc, w1.y * cc, w1.z * cc, w1.w * cc};
    float mx = wv[0];
#pragma unroll
    for (int i = 1; i < 8; i++) mx = fmaxf(mx, wv[i]);
#pragma unroll
    for (int o = 16; o; o >>= 1) mx = fmaxf(mx, __shfl_xor_sync(~0u, mx, o));
    float e[8], s = 0.f;
#pragma unroll
    for (int i = 0; i < 8; i++) { e[i] = expf(wv[i] - mx); s += e[i]; }
#pragma unroll
    for (int o = 16; o; o >>= 1) s += __shfl_xor_sync(~0u, s, o);
    float inv = 1.f / s;

    int a = actions[idx];
    float2* pdst = (float2*)(out + base + 258 + lane * 8);
    float2* odst = (float2*)(out + base + 514 + lane * 8);
#pragma unroll
    for (int i = 0; i < 4; i++) {
        pdst[i] = make_float2(e[2 * i] * inv, e[2 * i + 1] * inv);
        int l0 = lane * 8 + 2 * i;
        odst[i] = make_float2(l0 == a ? 1.f : 0.f, l0 + 1 == a ? 1.f : 0.f);
    }

    // v = h . Wc + bc
    const float4* hrow = (const float4*)(HD + idx * 256);
    const float4* wc = (const float4*)Wc;
    float4 h0v = hrow[lane * 2], h1v = hrow[lane * 2 + 1];
    float4 c0 = wc[lane * 2], c1 = wc[lane * 2 + 1];
    float d = h0v.x * c0.x + h0v.y * c0.y + h0v.z * c0.z + h0v.w * c0.w
            + h1v.x * c1.x + h1v.y * c1.y + h1v.z * c1.z + h1v.w * c1.w;
#pragma unroll
    for (int o = 16; o; o >>= 1) d += __shfl_xor_sync(~0u, d, o);
    if (lane == 0) {
        out[base + 0] = (float)a;
        out[base + 1] = d + bc[0];
    }
}

// ---------------------------------------------------------------------------
extern "C" void kernel_launch(void* const* d_in, const int* in_sizes, int n_in,
                              void* d_out, int out_size)
{
    const float* cond = (const float*)d_in[0];
    const float* M    = (const float*)d_in[1];
    const float* Km   = (const float*)d_in[2];
    const float* Cm   = (const float*)d_in[3];
    const float* h0   = (const float*)d_in[4];
    const float* p0   = (const float*)d_in[5];
    const float* W0   = (const float*)d_in[6];
    const float* b0   = (const float*)d_in[7];
    const float* W1   = (const float*)d_in[8];
    const float* b1   = (const float*)d_in[9];
    const float* W2   = (const float*)d_in[10];
    const float* b2   = (const float*)d_in[11];
    const float* W_ih = (const float*)d_in[12];
    const float* W_hh = (const float*)d_in[13];
    const float* b_ih = (const float*)d_in[14];
    const float* b_hh = (const float*)d_in[15];
    const float* Wa   = (const float*)d_in[16];
    const float* ba   = (const float*)d_in[17];
    const float* Wc   = (const float*)d_in[18];
    const float* bc   = (const float*)d_in[19];
    const int* actions = (const int*)d_in[20];
    float* out = (float*)d_out;

    float* base = nullptr;
    cudaGetSymbolAddress((void**)&base, g_scratch);
    float* XIN = base + XIN_OFF;
    float* XA  = base + XA_OFF;
    float* XB  = base + XB_OFF;
    float* GI  = base + GI_OFF;
    float* KB  = base + KB_OFF;
    float* WB  = base + WB_OFF;
    float* CC  = base + CC_OFF;
    float* HB  = base + HB_OFF;
    float* HD  = base + XIN_OFF;   // reuse XIN region after phase A

    void* bar_addr = nullptr;
    cudaGetSymbolAddress(&bar_addr, g_bar2);

    const int GRU_SMEM = 2 * 128 * 48 * 4 + 32 * HS_STRIDE * 4;  // 82432 B
    cudaFuncSetAttribute(gru_persistent,
                         cudaFuncAttributeMaxDynamicSharedMemorySize, GRU_SMEM);

    // phase A: inputs -> gi (fully parallel over T*N)
    t0_kernel<<<N_, 256>>>(p0, M, Cm, XIN, CC);
    gather_kernel<<<ROWS_ / 8, 256>>>(cond, M, Cm, actions, XIN, CC);
    gemm_kernel<false, true><<<dim3(ROWS_ / 128, 2, 1), 256>>>(
        XIN, W0, b0, XA, ROWS_, 256, 320, 320, 256, 256, 0, 0, 0);
    gemm_kernel<false, true><<<dim3(ROWS_ / 128, 2, 1), 256>>>(
        XA, W1, b1, XB, ROWS_, 256, 256, 256, 256, 256, 0, 0, 0);
    gemm_kernel<false, true><<<dim3(ROWS_ / 128, 2, 1), 256>>>(
        XB, W2, b2, XA, ROWS_, 256, 256, 256, 256, 256, 0, 0, 0);
    gemm_kernel<true, false><<<dim3(ROWS_ / 128, 6, 1), 256>>>(
        XA, W_ih, b_ih, GI, ROWS_, 768, 256, 256, 256, 768, 0, 0, 0);

    // phase B: persistent GRU (per-nt 16-block barriers)
    cudaMemsetAsync(bar_addr, 0, 16 * 32 * sizeof(unsigned));
    gru_persistent<<<GRU_BLOCKS, 256, GRU_SMEM>>>(GI, HB, h0, W_hh, b_hh, out, HD);

    // phase C: actor head (parallel again)
    gemm_kernel<false, false><<<dim3(ROWS_ / 128, 2, 1), 256>>>(
        HD, Wa, ba, KB, ROWS_, 256, 256, 256, 256, 256, 0, 0, 0);
    gemm_kernel<true, false><<<dim3(1, 2, N_), 256>>>(
        KB, Km, nullptr, WB, T_, 256, 256, N_ * 256, 256, 256,
        256L, (long)L_ * H_, (long)T_ * L_);
    epilogue_kernel<<<ROWS_ / 8, 256>>>(WB, CC, actions, Wc, bc, HD, out);
}

// round 5
// speedup vs baseline: 1.6649x; 1.1442x over previous
#include <cuda_runtime.h>
#include <math.h>

#define T_ 128
#define N_ 256
#define L_ 256
#define H_ 256
#define COND_ 64
#define ROWS_ (T_ * N_)   // 32768
#define OUTW_ 770         // 1 + 1 + H + L + L

typedef unsigned long long u64;

// ---------------- scratch (single __device__ symbol, no allocations) -------
// XIN (ROWS*320) is reused as HD (T*N*256 = 8.39M <= 10.49M) after phase A.
#define XIN_OFF 0L
#define XA_OFF  (XIN_OFF + (long)ROWS_ * 320)
#define XB_OFF  (XA_OFF  + (long)ROWS_ * 256)
#define GI_OFF  (XB_OFF  + (long)ROWS_ * 256)
#define KB_OFF  (GI_OFF  + (long)ROWS_ * 768)
#define WB_OFF  (KB_OFF  + (long)ROWS_ * 256)
#define CC_OFF  (WB_OFF  + (long)ROWS_ * 256)
#define SCRATCH_FLOATS (CC_OFF + (long)ROWS_)

__device__ float g_scratch[SCRATCH_FLOATS];
// per-group barriers: groups g=0..7; arrive at [g*32], epoch at [(8+g)*32]
__device__ unsigned g_bar2[16 * 32];

// ---------------- packed fp32x2 helpers (sm_103a) ---------------------------
#define FMA2(d, a, b) \
    asm("fma.rn.f32x2 %0, %1, %2, %0;" : "+l"(d) : "l"(a), "l"(b))
#define DUP2(d, x) \
    asm("mov.b64 %0, {%1, %1};" : "=l"(d) : "f"(x))
#define UNPACK2(lo, hi, v) \
    asm("mov.b64 {%0, %1}, %2;" : "=f"(lo), "=f"(hi) : "l"(v))

// ---------------------------------------------------------------------------
// t=0: p_init handling. Fast path: p0 row all-zero -> r0 = M[n,0,:], cc=C[n,0]
__global__ __launch_bounds__(256) void t0_kernel(
    const float* __restrict__ p0, const float* __restrict__ M,
    const float* __restrict__ C, float* __restrict__ XIN, float* __restrict__ CC)
{
    int n = blockIdx.x;
    int tid = threadIdx.x;
    float v = p0[(long)n * L_ + tid];
    int any = __syncthreads_or(v != 0.f);
    if (!any) {
        XIN[(long)n * 320 + 64 + tid] = M[(long)n * L_ * H_ + tid];
        if (tid == 0) CC[n] = C[(long)n * L_];
        return;
    }
    __shared__ float red[256];
    __shared__ float ps[256];
    ps[tid] = v;
    __syncthreads();
    float acc = 0.f;
    const float* Mn = M + (long)n * L_ * H_;
    for (int l = 0; l < L_; l++)
        acc = fmaf(ps[l], Mn[(long)l * H_ + tid], acc);
    XIN[(long)n * 320 + 64 + tid] = acc;
    red[tid] = ps[tid] * C[(long)n * L_ + tid];
    __syncthreads();
    for (int s = 128; s > 0; s >>= 1) {
        if (tid < s) red[tid] += red[tid + s];
        __syncthreads();
    }
    if (tid == 0) CC[n] = red[0];
}

// ---------------------------------------------------------------------------
__global__ __launch_bounds__(256) void gather_kernel(
    const float* __restrict__ cond, const float* __restrict__ M,
    const float* __restrict__ C, const int* __restrict__ actions,
    float* __restrict__ XIN, float* __restrict__ CC)
{
    int r = threadIdx.x >> 5, lane = threadIdx.x & 31;
    long idx = (long)blockIdx.x * 8 + r;    // t*N + n
    int t = (int)(idx / N_), n = (int)(idx % N_);
    float4* dst = (float4*)(XIN + idx * 320);
    const float4* csrc = (const float4*)(cond + idx * COND_);
    if (lane < 16) dst[lane] = csrc[lane];
    if (t > 0) {
        int a = actions[idx - N_];          // actions[t-1, n]
        const float4* msrc = (const float4*)(M + ((long)n * L_ + a) * H_);
#pragma unroll
        for (int i = 0; i < 2; i++) dst[16 + lane + i * 32] = msrc[lane + i * 32];
        if (lane == 0) CC[idx] = C[(long)n * L_ + a];
    }
}

// ---------------------------------------------------------------------------
// fp32 GEMM: 128x64 tile, 8x4/thread (row-pair f32x2 accs), frag-pipelined.
template <bool TRANSB, bool RELU>
__global__ __launch_bounds__(256, 2) void gemm_kernel(
    const float* __restrict__ A, const float* __restrict__ B,
    const float* __restrict__ bias, float* __restrict__ C,
    int M, int N, int K, int lda, int ldb, int ldc,
    long batchA, long batchB, long batchC)
{
    constexpr int BM = 128, BN = 64, BK = 16;
    __shared__ float As[2][BK][BM + 4];
    __shared__ float Bs[2][BK][BN + 4];

    long bz = blockIdx.z;
    A += bz * batchA; B += bz * batchB; C += bz * batchC;
    int m0 = blockIdx.x * BM, n0 = blockIdx.y * BN;
    int tid = threadIdx.x;
    int tx = tid & 15, ty = tid >> 4;   // 16x16 threads, 8 rows x 4 cols each

    // loader coordinates
    int am[2], ac[2];
#pragma unroll
    for (int i = 0; i < 2; i++) {
        int idx = tid + i * 256;
        am[i] = idx & 127; ac[i] = idx >> 7;
    }
    int bk = tid >> 4, bn4 = tid & 15;    // !TRANSB: (k, n-float4)
    int bn = tid & 63, bc2 = tid >> 6;    // TRANSB: (n, k-chunk)

    u64 acc[4][4];   // [row-pair p][col c]: rows (ty*8+2p, +1), col n0+tx*4+c
#pragma unroll
    for (int p = 0; p < 4; p++)
#pragma unroll
        for (int c = 0; c < 4; c++) acc[p][c] = 0ull;

    // prologue: stage tile 0 into buf 0
    {
#pragma unroll
        for (int i = 0; i < 2; i++) {
            float4 v = *(const float4*)&A[(long)(m0 + am[i]) * lda + ac[i] * 4];
            As[0][ac[i] * 4 + 0][am[i]] = v.x;
            As[0][ac[i] * 4 + 1][am[i]] = v.y;
            As[0][ac[i] * 4 + 2][am[i]] = v.z;
            As[0][ac[i] * 4 + 3][am[i]] = v.w;
        }
        if (!TRANSB) {
            float4 b = *(const float4*)&B[(long)bk * ldb + n0 + bn4 * 4];
            *(float4*)&Bs[0][bk][bn4 * 4] = b;
        } else {
            float4 b = *(const float4*)&B[(long)(n0 + bn) * ldb + bc2 * 4];
            Bs[0][bc2 * 4 + 0][bn] = b.x;
            Bs[0][bc2 * 4 + 1][bn] = b.y;
            Bs[0][bc2 * 4 + 2][bn] = b.z;
            Bs[0][bc2 * 4 + 3][bn] = b.w;
        }
    }
    __syncthreads();

    int nk = K / BK;
    float4 ra[2], rb;
    for (int it = 0; it < nk; it++) {
        int buf = it & 1;
        bool has_next = (it + 1 < nk);
        if (has_next) {
            int k0 = (it + 1) * BK;
#pragma unroll
            for (int i = 0; i < 2; i++)
                ra[i] = *(const float4*)&A[(long)(m0 + am[i]) * lda + k0 + ac[i] * 4];
            if (!TRANSB)
                rb = *(const float4*)&B[(long)(k0 + bk) * ldb + n0 + bn4 * 4];
            else
                rb = *(const float4*)&B[(long)(n0 + bn) * ldb + k0 + bc2 * 4];
        }
        // inner: register frag pipeline
        ulonglong2 a01c = *(const ulonglong2*)&As[buf][0][ty * 8];
        ulonglong2 a23c = *(const ulonglong2*)&As[buf][0][ty * 8 + 4];
        float4 bfc = *(const float4*)&Bs[buf][0][tx * 4];
#pragma unroll
        for (int k = 0; k < BK; k++) {
            ulonglong2 a01n, a23n; float4 bfn;
            if (k < BK - 1) {
                a01n = *(const ulonglong2*)&As[buf][k + 1][ty * 8];
                a23n = *(const ulonglong2*)&As[buf][k + 1][ty * 8 + 4];
                bfn = *(const float4*)&Bs[buf][k + 1][tx * 4];
            }
            u64 bd0, bd1, bd2, bd3;
            DUP2(bd0, bfc.x); DUP2(bd1, bfc.y); DUP2(bd2, bfc.z); DUP2(bd3, bfc.w);
            FMA2(acc[0][0], a01c.x, bd0); FMA2(acc[0][1], a01c.x, bd1);
            FMA2(acc[0][2], a01c.x, bd2); FMA2(acc[0][3], a01c.x, bd3);
            FMA2(acc[1][0], a01c.y, bd0); FMA2(acc[1][1], a01c.y, bd1);
            FMA2(acc[1][2], a01c.y, bd2); FMA2(acc[1][3], a01c.y, bd3);
            FMA2(acc[2][0], a23c.x, bd0); FMA2(acc[2][1], a23c.x, bd1);
            FMA2(acc[2][2], a23c.x, bd2); FMA2(acc[2][3], a23c.x, bd3);
            FMA2(acc[3][0], a23c.y, bd0); FMA2(acc[3][1], a23c.y, bd1);
            FMA2(acc[3][2], a23c.y, bd2); FMA2(acc[3][3], a23c.y, bd3);
            if (k < BK - 1) { a01c = a01n; a23c = a23n; bfc = bfn; }
        }
        if (has_next) {
            int nb = buf ^ 1;
#pragma unroll
            for (int i = 0; i < 2; i++) {
                As[nb][ac[i] * 4 + 0][am[i]] = ra[i].x;
                As[nb][ac[i] * 4 + 1][am[i]] = ra[i].y;
                As[nb][ac[i] * 4 + 2][am[i]] = ra[i].z;
                As[nb][ac[i] * 4 + 3][am[i]] = ra[i].w;
            }
            if (!TRANSB) {
                *(float4*)&Bs[nb][bk][bn4 * 4] = rb;
            } else {
                Bs[nb][bc2 * 4 + 0][bn] = rb.x;
                Bs[nb][bc2 * 4 + 1][bn] = rb.y;
                Bs[nb][bc2 * 4 + 2][bn] = rb.z;
                Bs[nb][bc2 * 4 + 3][bn] = rb.w;
            }
        }
        __syncthreads();
    }

    float4 bv = make_float4(0.f, 0.f, 0.f, 0.f);
    if (bias) bv = *(const float4*)&bias[n0 + tx * 4];
#pragma unroll
    for (int p = 0; p < 4; p++) {
        float r0[4], r1[4];
#pragma unroll
        for (int c = 0; c < 4; c++) UNPACK2(r0[c], r1[c], acc[p][c]);
        r0[0] += bv.x; r0[1] += bv.y; r0[2] += bv.z; r0[3] += bv.w;
        r1[0] += bv.x; r1[1] += bv.y; r1[2] += bv.z; r1[3] += bv.w;
        if (RELU) {
#pragma unroll
            for (int c = 0; c < 4; c++) {
                r0[c] = fmaxf(r0[c], 0.f);
                r1[c] = fmaxf(r1[c], 0.f);
            }
        }
        int m = m0 + ty * 8 + 2 * p;
        *(float4*)&C[(long)m * ldc + n0 + tx * 4] = *(float4*)r0;
        *(float4*)&C[(long)(m + 1) * ldc + n0 + tx * 4] = *(float4*)r1;
    }
}

// ---------------------------------------------------------------------------
// persistent GRU v3: 128 blocks (16 jt x 8 nt), k-split x2 inside the block.
// Thread (kg, jj, nn8): 4 n x 3 gates over 128 k. All smem reads LDS.128.
// h history stored once per step to dense HD[t][n][h].
#define GRU_BLOCKS 128
#define HSTR 260

__device__ __forceinline__ float sigmf(float x) { return 1.f / (1.f + expf(-x)); }

__global__ __launch_bounds__(256) void gru_persistent(
    const float* __restrict__ GI, const float* __restrict__ h0,
    const float* __restrict__ W_hh, const float* __restrict__ b_hh,
    float* __restrict__ HD)
{
    extern __shared__ float smem[];
    float4* w4 = (float4*)smem;                       // [64 chunks][48 rows]
    float* hs = smem + 4 * 64 * 48;                   // [32][HSTR]
    u64* redm = (u64*)(hs + 32 * HSTR);               // [128][12]

    int tid = threadIdx.x;
    int jt = blockIdx.x & 15, nt = blockIdx.x >> 4;
    int j0 = jt * 16, n0 = nt * 32;
    int kg = tid >> 7;                // k half: 0 -> k[0,128), 1 -> k[128,256)
    int lt = tid & 127;
    int jj = lt & 15, nn8 = lt >> 4;  // 0..15, 0..7
    int j = j0 + jj;

    unsigned* arr = &g_bar2[nt * 32];
    unsigned* ep  = &g_bar2[(8 + nt) * 32];

    // W slice -> smem: w4[c][r] = W_hh[g*256 + j0 + jr][4c .. 4c+3], r = g*16+jr
    for (int e = tid; e < 48 * 64; e += 256) {
        int c = e & 63, r = e >> 6;
        int g = r >> 4, jr = r & 15;
        w4[c * 48 + r] = *(const float4*)&W_hh[(long)(g * 256 + j0 + jr) * 256 + c * 4];
    }
    float bhr = b_hh[j], bhz = b_hh[256 + j], bhn = b_hh[512 + j];

    // prefetch gi(0) (kg0 only, it does the elementwise tail)
    float gi_r[4], gi_z[4], gi_n[4];
    if (kg == 0) {
#pragma unroll
        for (int i = 0; i < 4; i++) {
            const float* g = GI + ((long)(n0 + nn8 + 8 * i)) * 768;
            gi_r[i] = g[j]; gi_z[i] = g[256 + j]; gi_n[i] = g[512 + j];
        }
    }

    int cbase = kg * 32;

    for (int t = 0; t < T_; t++) {
        const float* hin = (t == 0) ? h0 : (HD + (long)(t - 1) * N_ * H_);
        float* hout = HD + (long)t * N_ * H_;

        // load h tile [n0, n0+32) x 256 into smem
        {
            int n = tid >> 3, f = tid & 7;
            const float4* src = (const float4*)(hin + (long)(n0 + n) * H_);
            float4* dst = (float4*)(hs + n * HSTR);
#pragma unroll
            for (int i = 0; i < 8; i++) dst[f + 8 * i] = src[f + 8 * i];
        }
        __syncthreads();   // sync1

        u64 acc[4][3];
#pragma unroll
        for (int i = 0; i < 4; i++)
#pragma unroll
            for (int g = 0; g < 3; g++) acc[i][g] = 0ull;

#pragma unroll 8
        for (int c = cbase; c < cbase + 32; c++) {
            const ulonglong2* wrow = (const ulonglong2*)(w4 + c * 48);
            ulonglong2 w0 = wrow[jj];
            ulonglong2 w1 = wrow[16 + jj];
            ulonglong2 w2 = wrow[32 + jj];
#pragma unroll
            for (int i = 0; i < 4; i++) {
                ulonglong2 hv = *(const ulonglong2*)(hs + (nn8 + 8 * i) * HSTR + c * 4);
                FMA2(acc[i][0], hv.x, w0.x); FMA2(acc[i][0], hv.y, w0.y);
                FMA2(acc[i][1], hv.x, w1.x); FMA2(acc[i][1], hv.y, w1.y);
                FMA2(acc[i][2], hv.x, w2.x); FMA2(acc[i][2], hv.y, w2.y);
            }
        }

        if (kg == 1) {
#pragma unroll
            for (int i = 0; i < 4; i++)
#pragma unroll
                for (int g = 0; g < 3; g++) redm[lt * 12 + i * 3 + g] = acc[i][g];
        }
        __syncthreads();   // sync2: partials visible

        if (kg == 0) {
#pragma unroll
            for (int i = 0; i < 4; i++) {
                float lo, hi, s[3];
#pragma unroll
                for (int g = 0; g < 3; g++) {
                    UNPACK2(lo, hi, acc[i][g]);
                    s[g] = lo + hi;
                    UNPACK2(lo, hi, redm[lt * 12 + i * 3 + g]);
                    s[g] += lo + hi;
                }
                int nl = nn8 + 8 * i;
                float rg = sigmf(gi_r[i] + s[0] + bhr);
                float z  = sigmf(gi_z[i] + s[1] + bhz);
                float nv = tanhf(gi_n[i] + rg * (s[2] + bhn));
                float hp = hs[nl * HSTR + j];
                float hn = (1.f - z) * nv + z * hp;
                hout[(long)(n0 + nl) * H_ + j] = hn;
            }
        }

        if (t < T_ - 1) {
            __syncthreads();   // sync3: HD stores issued, hs reads done
            if (tid == 0) {
                unsigned prev;
                asm volatile("atom.release.gpu.global.add.u32 %0, [%1], %2;"
                             : "=r"(prev) : "l"(arr), "r"(1u) : "memory");
                if (prev == (unsigned)((t + 1) * 16 - 1)) {
                    asm volatile("st.release.gpu.global.u32 [%0], %1;"
                                 :: "l"(ep), "r"((unsigned)(t + 1)) : "memory");
                }
            }
            if (kg == 0) {   // prefetch gi(t+1) while waiting
#pragma unroll
                for (int i = 0; i < 4; i++) {
                    const float* g = GI + ((long)(t + 1) * N_ + n0 + nn8 + 8 * i) * 768;
                    gi_r[i] = g[j]; gi_z[i] = g[256 + j]; gi_n[i] = g[512 + j];
                }
            }
            if (tid == 0) {
                unsigned e;
                do {
                    asm volatile("ld.acquire.gpu.global.u32 %0, [%1];"
                                 : "=r"(e) : "l"(ep) : "memory");
                } while (e < (unsigned)(t + 1));
            }
            __syncthreads();   // sync4
        }
    }
}

// ---------------------------------------------------------------------------
// warp-per-(t,n): h copy, softmax(w*cc), one-hot, action, value.
__global__ __launch_bounds__(256) void epilogue_kernel(
    const float* __restrict__ WB, const float* __restrict__ CC,
    const int* __restrict__ actions, const float* __restrict__ Wc,
    const float* __restrict__ bc, const float* __restrict__ HD,
    float* __restrict__ out)
{
    int wid = threadIdx.x >> 5, lane = threadIdx.x & 31;
    long idx = (long)blockIdx.x * 8 + wid;   // t*N + n
    int t = (int)(idx / N_), n = (int)(idx % N_);
    float cc = CC[idx];
    long base = idx * OUTW_;

    // h copy + value dot
    const float4* hrow = (const float4*)(HD + idx * 256);
    const float4* wc = (const float4*)Wc;
    float4 h0v = hrow[lane * 2], h1v = hrow[lane * 2 + 1];
    float4 c0 = wc[lane * 2], c1 = wc[lane * 2 + 1];
    float2* hdst = (float2*)(out + base + 2 + lane * 8);
    hdst[0] = make_float2(h0v.x, h0v.y);
    hdst[1] = make_float2(h0v.z, h0v.w);
    hdst[2] = make_float2(h1v.x, h1v.y);
    hdst[3] = make_float2(h1v.z, h1v.w);
    float d = h0v.x * c0.x + h0v.y * c0.y + h0v.z * c0.z + h0v.w * c0.w
            + h1v.x * c1.x + h1v.y * c1.y + h1v.z * c1.z + h1v.w * c1.w;
#pragma unroll
    for (int o = 16; o; o >>= 1) d += __shfl_xor_sync(~0u, d, o);

    const float4* wrow = (const float4*)(WB + ((long)n * T_ + t) * L_);
    float4 w0 = wrow[lane * 2], w1 = wrow[lane * 2 + 1];
    float wv[8] = {w0.x * cc, w0.y * cc, w0.z * cc, w0.w * cc,
                   w1.x * cc, w1.y * cc, w1.z * cc, w1.w * cc};
    float mx = wv[0];
#pragma unroll
    for (int i = 1; i < 8; i++) mx = fmaxf(mx, wv[i]);
#pragma unroll
    for (int o = 16; o; o >>= 1) mx = fmaxf(mx, __shfl_xor_sync(~0u, mx, o));
    float e[8], s = 0.f;
#pragma unroll
    for (int i = 0; i < 8; i++) { e[i] = expf(wv[i] - mx); s += e[i]; }
#pragma unroll
    for (int o = 16; o; o >>= 1) s += __shfl_xor_sync(~0u, s, o);
    float inv = 1.f / s;

    int a = actions[idx];
    float2* pdst = (float2*)(out + base + 258 + lane * 8);
    float2* odst = (float2*)(out + base + 514 + lane * 8);
#pragma unroll
    for (int i = 0; i < 4; i++) {
        pdst[i] = make_float2(e[2 * i] * inv, e[2 * i + 1] * inv);
        int l0 = lane * 8 + 2 * i;
        odst[i] = make_float2(l0 == a ? 1.f : 0.f, l0 + 1 == a ? 1.f : 0.f);
    }
    if (lane == 0) {
        out[base + 0] = (float)a;
        out[base + 1] = d + bc[0];
    }
}

// ---------------------------------------------------------------------------
extern "C" void kernel_launch(void* const* d_in, const int* in_sizes, int n_in,
                              void* d_out, int out_size)
{
    const float* cond = (const float*)d_in[0];
    const float* M    = (const float*)d_in[1];
    const float* Km   = (const float*)d_in[2];
    const float* Cm   = (const float*)d_in[3];
    const float* h0   = (const float*)d_in[4];
    const float* p0   = (const float*)d_in[5];
    const float* W0   = (const float*)d_in[6];
    const float* b0   = (const float*)d_in[7];
    const float* W1   = (const float*)d_in[8];
    const float* b1   = (const float*)d_in[9];
    const float* W2   = (const float*)d_in[10];
    const float* b2   = (const float*)d_in[11];
    const float* W_ih = (const float*)d_in[12];
    const float* W_hh = (const float*)d_in[13];
    const float* b_ih = (const float*)d_in[14];
    const float* b_hh = (const float*)d_in[15];
    const float* Wa   = (const float*)d_in[16];
    const float* ba   = (const float*)d_in[17];
    const float* Wc   = (const float*)d_in[18];
    const float* bc   = (const float*)d_in[19];
    const int* actions = (const int*)d_in[20];
    float* out = (float*)d_out;

    float* base = nullptr;
    cudaGetSymbolAddress((void**)&base, g_scratch);
    float* XIN = base + XIN_OFF;
    float* XA  = base + XA_OFF;
    float* XB  = base + XB_OFF;
    float* GI  = base + GI_OFF;
    float* KB  = base + KB_OFF;
    float* WB  = base + WB_OFF;
    float* CC  = base + CC_OFF;
    float* HD  = base + XIN_OFF;   // reuse XIN region after phase A

    void* bar_addr = nullptr;
    cudaGetSymbolAddress(&bar_addr, g_bar2);

    const int GRU_SMEM = 4 * 64 * 48 * 4 + 32 * HSTR * 4 + 128 * 12 * 8; // 94720
    cudaFuncSetAttribute(gru_persistent,
                         cudaFuncAttributeMaxDynamicSharedMemorySize, GRU_SMEM);

    // phase A: inputs -> gi (fully parallel over T*N)
    t0_kernel<<<N_, 256>>>(p0, M, Cm, XIN, CC);
    gather_kernel<<<ROWS_ / 8, 256>>>(cond, M, Cm, actions, XIN, CC);
    gemm_kernel<false, true><<<dim3(ROWS_ / 128, 4, 1), 256>>>(
        XIN, W0, b0, XA, ROWS_, 256, 320, 320, 256, 256, 0, 0, 0);
    gemm_kernel<false, true><<<dim3(ROWS_ / 128, 4, 1), 256>>>(
        XA, W1, b1, XB, ROWS_, 256, 256, 256, 256, 256, 0, 0, 0);
    gemm_kernel<false, true><<<dim3(ROWS_ / 128, 4, 1), 256>>>(
        XB, W2, b2, XA, ROWS_, 256, 256, 256, 256, 256, 0, 0, 0);
    gemm_kernel<true, false><<<dim3(ROWS_ / 128, 12, 1), 256>>>(
        XA, W_ih, b_ih, GI, ROWS_, 768, 256, 256, 256, 768, 0, 0, 0);

    // phase B: persistent GRU (per-nt 16-block barriers)
    cudaMemsetAsync(bar_addr, 0, 16 * 32 * sizeof(unsigned));
    gru_persistent<<<GRU_BLOCKS, 256, GRU_SMEM>>>(GI, h0, W_hh, b_hh, HD);

    // phase C: actor head (parallel again)
    gemm_kernel<false, false><<<dim3(ROWS_ / 128, 4, 1), 256>>>(
        HD, Wa, ba, KB, ROWS_, 256, 256, 256, 256, 256, 0, 0, 0);
    gemm_kernel<true, false><<<dim3(1, 4, N_), 256>>>(
        KB, Km, nullptr, WB, T_, 256, 256, N_ * 256, 256, 256,
        256L, (long)L_ * H_, (long)T_ * L_);
    epilogue_kernel<<<ROWS_ / 8, 256>>>(WB, CC, actions, Wc, bc, HD, out);
}